// round 2
// baseline (speedup 1.0000x reference)
#include <cuda_runtime.h>
#include <cstdint>

#define SEQ 2048
#define BATCH 4
#define EMB 1024
#define NHEAD 16
#define HDIM 64
#define MROWS (SEQ*BATCH)

// scratch (static device arrays: allocation-free rule)
__device__ float g_q[BATCH*NHEAD*SEQ*HDIM];
__device__ float g_k[BATCH*NHEAD*SEQ*HDIM];
__device__ float g_v[BATCH*NHEAD*SEQ*HDIM];
__device__ float g_attn[MROWS*EMB];

// fast exp via FMA-pipe polynomial (avoids MUFU.EX2 throughput wall).
// valid for x <= 0 (always true here); rel err ~2e-6.
__device__ __forceinline__ float fexp(float x) {
    float y = x * 1.4426950408889634f;
    y = fmaxf(y, -120.0f);
    float t = y + 12582912.0f;          // round-to-nearest-int via magic number
    float nf = t - 12582912.0f;
    float f = y - nf;                   // f in [-0.5, 0.5]
    int n = __float_as_int(t) - 0x4B400000;
    float p =      1.3333558146e-3f;
    p = fmaf(p, f, 9.6181291076e-3f);
    p = fmaf(p, f, 5.5504108664e-2f);
    p = fmaf(p, f, 2.4022650696e-1f);
    p = fmaf(p, f, 6.9314718056e-1f);
    p = fmaf(p, f, 1.0f);
    return p * __int_as_float((n + 127) << 23);
}

// C[M,N] = A[M,K] @ W[N,K]^T (+bias), 128x128 tile, BK=8, 8x8 microtile.
// MODE 0: A = Ain (query), epilogue routes qkv -> g_q/g_k/g_v in [B,H,S,D], scales q.
// MODE 1: A = g_attn, plain epilogue to out.
template<int MODE>
__global__ void __launch_bounds__(256)
gemm128(const float* __restrict__ Ain, const float* __restrict__ W,
        const float* __restrict__ bias, float* __restrict__ out)
{
    __shared__ __align__(16) float As[8][128];
    __shared__ __align__(16) float Bs[8][128];
    const int t  = threadIdx.x;
    const int m0 = blockIdx.y * 128;
    const int n0 = blockIdx.x * 128;
    const int lr = t >> 1;
    const int lq = (t & 1) * 4;
    const int ty = t >> 4, tx = t & 15;

    const float* A  = (MODE == 0) ? Ain : (const float*)g_attn;
    const float* Ap = A + (size_t)(m0 + lr) * EMB + lq;
    const float* Wp = W + (size_t)(n0 + lr) * EMB + lq;

    float acc[8][8];
#pragma unroll
    for (int i = 0; i < 8; i++)
#pragma unroll
        for (int j = 0; j < 8; j++) acc[i][j] = 0.f;

    for (int kb = 0; kb < EMB; kb += 8) {
        float4 a4 = *(const float4*)(Ap + kb);
        float4 b4 = *(const float4*)(Wp + kb);
        __syncthreads();
        As[lq+0][lr] = a4.x; As[lq+1][lr] = a4.y; As[lq+2][lr] = a4.z; As[lq+3][lr] = a4.w;
        Bs[lq+0][lr] = b4.x; Bs[lq+1][lr] = b4.y; Bs[lq+2][lr] = b4.z; Bs[lq+3][lr] = b4.w;
        __syncthreads();
#pragma unroll
        for (int kk = 0; kk < 8; kk++) {
            float4 a0 = *(const float4*)&As[kk][ty*8];
            float4 a1 = *(const float4*)&As[kk][ty*8+4];
            float4 b0 = *(const float4*)&Bs[kk][tx*8];
            float4 b1 = *(const float4*)&Bs[kk][tx*8+4];
            float av[8] = {a0.x,a0.y,a0.z,a0.w,a1.x,a1.y,a1.z,a1.w};
            float bv[8] = {b0.x,b0.y,b0.z,b0.w,b1.x,b1.y,b1.z,b1.w};
#pragma unroll
            for (int i = 0; i < 8; i++)
#pragma unroll
                for (int j = 0; j < 8; j++)
                    acc[i][j] = fmaf(av[i], bv[j], acc[i][j]);
        }
    }

    if (MODE == 0) {
#pragma unroll
        for (int i = 0; i < 8; i++) {
            int m = m0 + ty*8 + i;
            int s = m >> 2, b = m & 3;
#pragma unroll
            for (int j = 0; j < 8; j++) {
                int n = n0 + tx*8 + j;
                float v = acc[i][j] + bias[n];
                int which = n >> 10;
                int e = n & 1023;
                int h = e >> 6, d = e & 63;
                float* dst = (which == 0) ? g_q : (which == 1) ? g_k : g_v;
                if (which == 0) v *= 0.125f;           // D^-0.5
                dst[(((b*NHEAD + h)*SEQ) + s)*HDIM + d] = v;
            }
        }
    } else {
#pragma unroll
        for (int i = 0; i < 8; i++) {
            int m = m0 + ty*8 + i;
#pragma unroll
            for (int j = 0; j < 8; j++) {
                int n = n0 + tx*8 + j;
                out[(size_t)m*EMB + n] = acc[i][j] + bias[n];
            }
        }
    }
}

// Flash attention: one block handles 128 q-rows of one (b,h); iterates 64-wide k tiles.
// 256 threads, 16x16 grid, 8x4 microtiles for both QK^T and PV.
__global__ void __launch_bounds__(256)
attn_kernel(const float* __restrict__ mask, const unsigned char* __restrict__ pad)
{
    extern __shared__ __align__(16) float sm[];
    float* Qs = sm;                  // [128][68]
    float* Kt = sm + 128*68;         // [64][68]  (transposed: Kt[d][c])
    float* Vs = Kt + 64*68;          // [64][68]
    float* Ps = Vs + 64*68;          // [128][68]

    const int t  = threadIdx.x;
    const int ty = t >> 4, tx = t & 15;
    const int qt = blockIdx.x;       // 0..15
    const int bh = blockIdx.y;       // 0..63
    const int b  = bh >> 4;
    const int h  = bh & 15;
    const float* Qg = g_q + (size_t)bh*SEQ*HDIM + qt*128*HDIM;
    const float* Kg = g_k + (size_t)bh*SEQ*HDIM;
    const float* Vg = g_v + (size_t)bh*SEQ*HDIM;
    const float* Mg = mask + (size_t)b*SEQ*SEQ + (size_t)(qt*128)*SEQ;
    const unsigned char* Pg = pad + b*SEQ;

    {   // load Q tile once: 128x64
        int row = t >> 1;
        int hc  = (t & 1) * 32;
        const float4* src = (const float4*)(Qg + row*HDIM + hc);
        float4* dq = (float4*)(Qs + row*68 + hc);
#pragma unroll
        for (int ff = 0; ff < 8; ff++) dq[ff] = src[ff];
    }

    float m_i[8], l_i[8], o[8][4];
#pragma unroll
    for (int i = 0; i < 8; i++) {
        m_i[i] = -1e30f; l_i[i] = 0.f;
#pragma unroll
        for (int j = 0; j < 4; j++) o[i][j] = 0.f;
    }
    const int r0 = ty*8;
    const int c0 = tx*4;

    for (int kt = 0; kt < SEQ/64; kt++) {
        __syncthreads();             // previous tile's Kt/Vs/Ps reads done
        {   // load K tile (transposed) + V tile
            int c   = t >> 2;
            int dq0 = (t & 3) * 4;
#pragma unroll
            for (int rr = 0; rr < 4; rr++) {
                int dd = dq0 + rr*16;
                float4 k4 = *(const float4*)(Kg + (size_t)(kt*64 + c)*HDIM + dd);
                Kt[(dd+0)*68 + c] = k4.x;
                Kt[(dd+1)*68 + c] = k4.y;
                Kt[(dd+2)*68 + c] = k4.z;
                Kt[(dd+3)*68 + c] = k4.w;
                float4 v4 = *(const float4*)(Vg + (size_t)(kt*64 + c)*HDIM + dd);
                *(float4*)(Vs + c*68 + dd) = v4;
            }
        }
        __syncthreads();

        // ---- scores S = Q K^T (8x4 per thread) ----
        float s[8][4];
#pragma unroll
        for (int i = 0; i < 8; i++)
#pragma unroll
            for (int j = 0; j < 4; j++) s[i][j] = 0.f;

#pragma unroll 2
        for (int d4 = 0; d4 < HDIM; d4 += 4) {
            float kkv[4][4];
#pragma unroll
            for (int u = 0; u < 4; u++) {
                float4 k4 = *(const float4*)(Kt + (d4+u)*68 + c0);
                kkv[u][0]=k4.x; kkv[u][1]=k4.y; kkv[u][2]=k4.z; kkv[u][3]=k4.w;
            }
#pragma unroll
            for (int i = 0; i < 8; i++) {
                float4 q4 = *(const float4*)(Qs + (r0+i)*68 + d4);
#pragma unroll
                for (int j = 0; j < 4; j++) {
                    s[i][j] = fmaf(q4.x, kkv[0][j],
                              fmaf(q4.y, kkv[1][j],
                              fmaf(q4.z, kkv[2][j],
                              fmaf(q4.w, kkv[3][j], s[i][j]))));
                }
            }
        }

        // ---- add mask, padding, online softmax ----
        int kg0 = kt*64 + c0;
        uchar4 pm4 = *(const uchar4*)(Pg + kg0);
#pragma unroll
        for (int i = 0; i < 8; i++) {
            float4 mk = *(const float4*)(Mg + (size_t)(r0+i)*SEQ + kg0);
            s[i][0] = pm4.x ? -10000.f : s[i][0] + mk.x;
            s[i][1] = pm4.y ? -10000.f : s[i][1] + mk.y;
            s[i][2] = pm4.z ? -10000.f : s[i][2] + mk.z;
            s[i][3] = pm4.w ? -10000.f : s[i][3] + mk.w;
        }

#pragma unroll
        for (int i = 0; i < 8; i++) {
            float mx = fmaxf(fmaxf(s[i][0], s[i][1]), fmaxf(s[i][2], s[i][3]));
            mx = fmaxf(mx, __shfl_xor_sync(0xffffffffu, mx, 1));
            mx = fmaxf(mx, __shfl_xor_sync(0xffffffffu, mx, 2));
            mx = fmaxf(mx, __shfl_xor_sync(0xffffffffu, mx, 4));
            mx = fmaxf(mx, __shfl_xor_sync(0xffffffffu, mx, 8));
            float mnew = fmaxf(m_i[i], mx);
            float sc = fexp(m_i[i] - mnew);
            m_i[i] = mnew;
            float rs = 0.f;
#pragma unroll
            for (int j = 0; j < 4; j++) {
                float p = fexp(s[i][j] - mnew);
                s[i][j] = p;
                rs += p;
            }
            rs += __shfl_xor_sync(0xffffffffu, rs, 1);
            rs += __shfl_xor_sync(0xffffffffu, rs, 2);
            rs += __shfl_xor_sync(0xffffffffu, rs, 4);
            rs += __shfl_xor_sync(0xffffffffu, rs, 8);
            l_i[i] = l_i[i]*sc + rs;
            o[i][0] *= sc; o[i][1] *= sc; o[i][2] *= sc; o[i][3] *= sc;
            *(float4*)(Ps + (r0+i)*68 + c0) = make_float4(s[i][0], s[i][1], s[i][2], s[i][3]);
        }
        __syncthreads();

        // ---- O += P V ----
#pragma unroll 2
        for (int jj = 0; jj < 64; jj += 4) {
            float vv[4][4];
#pragma unroll
            for (int u = 0; u < 4; u++) {
                float4 v4 = *(const float4*)(Vs + (jj+u)*68 + c0);
                vv[u][0]=v4.x; vv[u][1]=v4.y; vv[u][2]=v4.z; vv[u][3]=v4.w;
            }
#pragma unroll
            for (int i = 0; i < 8; i++) {
                float4 p4 = *(const float4*)(Ps + (r0+i)*68 + jj);
#pragma unroll
                for (int j = 0; j < 4; j++) {
                    o[i][j] = fmaf(p4.x, vv[0][j],
                              fmaf(p4.y, vv[1][j],
                              fmaf(p4.z, vv[2][j],
                              fmaf(p4.w, vv[3][j], o[i][j]))));
                }
            }
        }
    }

    // ---- normalize + write to [S,B,E] layout for the output GEMM ----
    const int sg0 = qt*128 + r0;
#pragma unroll
    for (int i = 0; i < 8; i++) {
        float inv = 1.0f / l_i[i];
        float4 r4 = make_float4(o[i][0]*inv, o[i][1]*inv, o[i][2]*inv, o[i][3]*inv);
        *(float4*)(g_attn + (size_t)((sg0+i)*BATCH + b)*EMB + h*HDIM + c0) = r4;
    }
}

extern "C" void kernel_launch(void* const* d_in, const int* in_sizes, int n_in,
                              void* d_out, int out_size)
{
    const float* query          = (const float*)d_in[0];
    const float* amask          = (const float*)d_in[1];
    const unsigned char* pmask  = (const unsigned char*)d_in[2];
    const float* W_in           = (const float*)d_in[3];
    const float* b_in           = (const float*)d_in[4];
    const float* W_out          = (const float*)d_in[5];
    const float* b_out          = (const float*)d_in[6];
    float* out = (float*)d_out;
    (void)in_sizes; (void)n_in; (void)out_size;

    // 104448 B dynamic smem for attention (2 blocks/SM within 227KB)
    cudaFuncSetAttribute(attn_kernel, cudaFuncAttributeMaxDynamicSharedMemorySize, 104448);

    // 1) QKV projection, fused routing to [B,H,S,D] + q scaling
    gemm128<0><<<dim3(24, 64), 256>>>(query, W_in, b_in, nullptr);
    // 2) flash attention
    attn_kernel<<<dim3(16, 64), 256, 104448>>>(amask, pmask);
    // 3) output projection
    gemm128<1><<<dim3(8, 64), 256>>>(nullptr, W_out, b_out, out);
}

// round 3
// speedup vs baseline: 1.9701x; 1.9701x over previous
#include <cuda_runtime.h>
#include <cstdint>

#define SEQ 2048
#define BATCH 4
#define EMB 1024
#define NHEAD 16
#define HDIM 64

// scratch (static device arrays: allocation-free rule)
__device__ float g_q[BATCH*NHEAD*SEQ*HDIM];
__device__ float g_k[BATCH*NHEAD*SEQ*HDIM];
__device__ float g_v[BATCH*NHEAD*SEQ*HDIM];
__device__ float g_attn[SEQ*BATCH*EMB];

// round-to-nearest tf32 (halves truncation error vs raw HMMA truncation)
__device__ __forceinline__ uint32_t f2tf(float x) {
    uint32_t r;
    asm("cvt.rna.tf32.f32 %0, %1;" : "=r"(r) : "f"(x));
    return r;
}

// m16n8k8 row.col tf32 mma, fp32 accumulate in place
__device__ __forceinline__ void mma8(float* c, const uint32_t* a, const uint32_t* b) {
    asm volatile(
        "mma.sync.aligned.m16n8k8.row.col.f32.tf32.tf32.f32 "
        "{%0,%1,%2,%3}, {%4,%5,%6,%7}, {%8,%9}, {%0,%1,%2,%3};"
        : "+f"(c[0]), "+f"(c[1]), "+f"(c[2]), "+f"(c[3])
        : "r"(a[0]), "r"(a[1]), "r"(a[2]), "r"(a[3]), "r"(b[0]), "r"(b[1]));
}

// fast exp on the FMA pipe (avoids MUFU.EX2 wall); valid for x <= 0
__device__ __forceinline__ float fexp(float x) {
    float y = x * 1.4426950408889634f;
    y = fmaxf(y, -120.0f);
    float t = y + 12582912.0f;
    float nf = t - 12582912.0f;
    float f = y - nf;
    int n = __float_as_int(t) - 0x4B400000;
    float p =      1.3333558146e-3f;
    p = fmaf(p, f, 9.6181291076e-3f);
    p = fmaf(p, f, 5.5504108664e-2f);
    p = fmaf(p, f, 2.4022650696e-1f);
    p = fmaf(p, f, 6.9314718056e-1f);
    p = fmaf(p, f, 1.0f);
    return p * __int_as_float((n + 127) << 23);
}

// C[M,N] = A[M,K] @ W[N,K]^T (+bias). 128x128 block tile, BK=32, tf32 mma.
// Warps 4(M)x2(N): each warp 32x64 = 2 m16-tiles x 8 n8-tiles.
// MODE 0: A=query, epilogue routes qkv -> g_q/g_k/g_v [B,H,S,D], scales q.
// MODE 1: A=g_attn, epilogue to out.
template<int MODE>
__global__ void __launch_bounds__(256)
gemm_tf32(const float* __restrict__ Ain, const float* __restrict__ W,
          const float* __restrict__ bias, float* __restrict__ out)
{
    __shared__ float As[128][36];   // [m][k], stride 36 -> (4g+q) conflict-free frag loads
    __shared__ float Bs[128][36];   // [n][k]

    const int t    = threadIdx.x;
    const int lane = t & 31, g = lane >> 2, q = lane & 3;
    const int wid  = t >> 5, wm = wid >> 1, wn = wid & 1;
    const int m0   = blockIdx.y * 128;
    const int n0   = blockIdx.x * 128;

    const float* A = (MODE == 0) ? Ain : (const float*)g_attn;
    const int lrow = t >> 1;
    const int lcb  = (t & 1) * 16;
    const float* Ap = A + (size_t)(m0 + lrow) * EMB + lcb;
    const float* Wp = W + (size_t)(n0 + lrow) * EMB + lcb;

    float c[2][8][4];
#pragma unroll
    for (int mt = 0; mt < 2; mt++)
#pragma unroll
        for (int nt = 0; nt < 8; nt++)
#pragma unroll
            for (int r = 0; r < 4; r++) c[mt][nt][r] = 0.f;

    float4 pa[4], pb[4];
#pragma unroll
    for (int i = 0; i < 4; i++) {
        pa[i] = *(const float4*)(Ap + i * 4);
        pb[i] = *(const float4*)(Wp + i * 4);
    }

    for (int kb = 0; kb < EMB; kb += 32) {
        __syncthreads();
#pragma unroll
        for (int i = 0; i < 4; i++) {
            float* da = &As[lrow][lcb + i * 4];
            float* db = &Bs[lrow][lcb + i * 4];
            da[0] = __uint_as_float(f2tf(pa[i].x));
            da[1] = __uint_as_float(f2tf(pa[i].y));
            da[2] = __uint_as_float(f2tf(pa[i].z));
            da[3] = __uint_as_float(f2tf(pa[i].w));
            db[0] = __uint_as_float(f2tf(pb[i].x));
            db[1] = __uint_as_float(f2tf(pb[i].y));
            db[2] = __uint_as_float(f2tf(pb[i].z));
            db[3] = __uint_as_float(f2tf(pb[i].w));
        }
        __syncthreads();
        if (kb + 32 < EMB) {
#pragma unroll
            for (int i = 0; i < 4; i++) {
                pa[i] = *(const float4*)(Ap + kb + 32 + i * 4);
                pb[i] = *(const float4*)(Wp + kb + 32 + i * 4);
            }
        }
#pragma unroll
        for (int ks = 0; ks < 4; ks++) {
            const int k0 = ks * 8;
            uint32_t af[2][4], bf[8][2];
#pragma unroll
            for (int mt = 0; mt < 2; mt++) {
                const int mb = wm * 32 + mt * 16;
                af[mt][0] = __float_as_uint(As[mb + g    ][k0 + q]);
                af[mt][1] = __float_as_uint(As[mb + g + 8][k0 + q]);
                af[mt][2] = __float_as_uint(As[mb + g    ][k0 + q + 4]);
                af[mt][3] = __float_as_uint(As[mb + g + 8][k0 + q + 4]);
            }
#pragma unroll
            for (int nt = 0; nt < 8; nt++) {
                const int nb = wn * 64 + nt * 8 + g;
                bf[nt][0] = __float_as_uint(Bs[nb][k0 + q]);
                bf[nt][1] = __float_as_uint(Bs[nb][k0 + q + 4]);
            }
#pragma unroll
            for (int mt = 0; mt < 2; mt++)
#pragma unroll
                for (int nt = 0; nt < 8; nt++)
                    mma8(c[mt][nt], af[mt], bf[nt]);
        }
    }

#pragma unroll
    for (int mt = 0; mt < 2; mt++) {
#pragma unroll
        for (int nt = 0; nt < 8; nt++) {
#pragma unroll
            for (int r = 0; r < 4; r++) {
                const int m = m0 + wm * 32 + mt * 16 + g + ((r >= 2) ? 8 : 0);
                const int n = n0 + wn * 64 + nt * 8 + q * 2 + (r & 1);
                float v = c[mt][nt][r] + bias[n];
                if (MODE == 0) {
                    const int s = m >> 2, b = m & 3;
                    const int which = n >> 10;
                    const int e = n & 1023;
                    const int h = e >> 6, d = e & 63;
                    float* dst = (which == 0) ? g_q : (which == 1) ? g_k : g_v;
                    if (which == 0) v *= 0.125f;   // D^-0.5
                    dst[(((b * NHEAD + h) * SEQ) + s) * HDIM + d] = v;
                } else {
                    out[(size_t)m * EMB + n] = v;
                }
            }
        }
    }
}

// Flash attention with tf32 mma. Block: 128 q-rows of one (b,h), 256 threads.
// Each warp owns 16 q-rows; k-tiles of 64. Q fragments live in registers.
__global__ void __launch_bounds__(256)
attn_tf32(const float* __restrict__ mask, const unsigned char* __restrict__ pad)
{
    extern __shared__ float sm[];
    float* Ks = sm;                 // [64][68]  K rows [kcol][d]
    float* Vt = sm + 64 * 68;       // [64][68]  V transposed [d][kcol]
    float* Ps = sm + 2 * 64 * 68;   // [128][68] probabilities

    const int t = threadIdx.x, lane = t & 31, g = lane >> 2, q = lane & 3;
    const int wid = t >> 5;
    const int qt = blockIdx.x;      // 0..15
    const int bh = blockIdx.y;      // 0..63
    const int b = bh >> 4, head = bh & 15;

    const float* Qg = g_q + (size_t)bh * SEQ * HDIM;
    const float* Kg = g_k + (size_t)bh * SEQ * HDIM;
    const float* Vg = g_v + (size_t)bh * SEQ * HDIM;
    const float* Mg = mask + (size_t)b * SEQ * SEQ + (size_t)(qt * 128) * SEQ;
    const unsigned char* Pg = pad + b * SEQ;

    // Q fragments for this warp's 16 rows, held in registers for all k-tiles
    uint32_t qf[8][4];
    {
        const int r0 = qt * 128 + wid * 16;
#pragma unroll
        for (int ks = 0; ks < 8; ks++) {
            const int k0 = ks * 8;
            qf[ks][0] = f2tf(Qg[(size_t)(r0 + g    ) * HDIM + k0 + q]);
            qf[ks][1] = f2tf(Qg[(size_t)(r0 + g + 8) * HDIM + k0 + q]);
            qf[ks][2] = f2tf(Qg[(size_t)(r0 + g    ) * HDIM + k0 + q + 4]);
            qf[ks][3] = f2tf(Qg[(size_t)(r0 + g + 8) * HDIM + k0 + q + 4]);
        }
    }

    float o[8][4];
#pragma unroll
    for (int nt = 0; nt < 8; nt++)
#pragma unroll
        for (int r = 0; r < 4; r++) o[nt][r] = 0.f;
    float m_i[2] = {-1e30f, -1e30f};
    float l_i[2] = {0.f, 0.f};

    for (int kt = 0; kt < SEQ / 64; kt++) {
        __syncthreads();
        {   // load K tile [kcol][d] + V tile transposed [d][kcol], cvt to tf32
            const int row = t >> 2;
            const int cb  = (t & 3) * 16;
            const float4* ks4 = (const float4*)(Kg + (size_t)(kt * 64 + row) * HDIM + cb);
            float* kd = Ks + row * 68 + cb;
#pragma unroll
            for (int i = 0; i < 4; i++) {
                float4 k4 = ks4[i];
                kd[i * 4 + 0] = __uint_as_float(f2tf(k4.x));
                kd[i * 4 + 1] = __uint_as_float(f2tf(k4.y));
                kd[i * 4 + 2] = __uint_as_float(f2tf(k4.z));
                kd[i * 4 + 3] = __uint_as_float(f2tf(k4.w));
            }
            const int c = t >> 2, d0 = (t & 3) * 4;
#pragma unroll
            for (int rr = 0; rr < 4; rr++) {
                const int dd = d0 + rr * 16;
                float4 v4 = *(const float4*)(Vg + (size_t)(kt * 64 + c) * HDIM + dd);
                Vt[(dd + 0) * 68 + c] = __uint_as_float(f2tf(v4.x));
                Vt[(dd + 1) * 68 + c] = __uint_as_float(f2tf(v4.y));
                Vt[(dd + 2) * 68 + c] = __uint_as_float(f2tf(v4.z));
                Vt[(dd + 3) * 68 + c] = __uint_as_float(f2tf(v4.w));
            }
        }
        __syncthreads();

        // ---- S = Q K^T ----
        float s[8][4];
#pragma unroll
        for (int nt = 0; nt < 8; nt++)
#pragma unroll
            for (int r = 0; r < 4; r++) s[nt][r] = 0.f;
#pragma unroll
        for (int ks = 0; ks < 8; ks++) {
            const int k0 = ks * 8;
#pragma unroll
            for (int nt = 0; nt < 8; nt++) {
                uint32_t bf[2];
                bf[0] = __float_as_uint(Ks[(nt * 8 + g) * 68 + k0 + q]);
                bf[1] = __float_as_uint(Ks[(nt * 8 + g) * 68 + k0 + q + 4]);
                mma8(s[nt], qf[ks], bf);
            }
        }

        // ---- mask + padding + online softmax (C layout: 2 rows/thread) ----
#pragma unroll
        for (int hh = 0; hh < 2; hh++) {
            const int row = wid * 16 + g + hh * 8;
            const float* Mrow = Mg + (size_t)row * SEQ + kt * 64 + 2 * q;
            const unsigned char* Prow = Pg + kt * 64 + 2 * q;
            float mx = -1e30f;
#pragma unroll
            for (int nt = 0; nt < 8; nt++) {
                float2 mk = *(const float2*)(Mrow + nt * 8);
                const unsigned char p0 = Prow[nt * 8], p1 = Prow[nt * 8 + 1];
                float v0 = p0 ? -10000.f : s[nt][hh * 2]     + mk.x;
                float v1 = p1 ? -10000.f : s[nt][hh * 2 + 1] + mk.y;
                s[nt][hh * 2]     = v0;
                s[nt][hh * 2 + 1] = v1;
                mx = fmaxf(mx, fmaxf(v0, v1));
            }
            mx = fmaxf(mx, __shfl_xor_sync(0xffffffffu, mx, 1));
            mx = fmaxf(mx, __shfl_xor_sync(0xffffffffu, mx, 2));
            const float mnew = fmaxf(m_i[hh], mx);
            const float sc = fexp(m_i[hh] - mnew);
            m_i[hh] = mnew;
            float rs = 0.f;
            float* Pw = Ps + row * 68 + 2 * q;
#pragma unroll
            for (int nt = 0; nt < 8; nt++) {
                float p0 = fexp(s[nt][hh * 2]     - mnew);
                float p1 = fexp(s[nt][hh * 2 + 1] - mnew);
                rs += p0 + p1;
                float2 st;
                st.x = __uint_as_float(f2tf(p0));
                st.y = __uint_as_float(f2tf(p1));
                *(float2*)(Pw + nt * 8) = st;
                o[nt][hh * 2]     *= sc;
                o[nt][hh * 2 + 1] *= sc;
            }
            rs += __shfl_xor_sync(0xffffffffu, rs, 1);
            rs += __shfl_xor_sync(0xffffffffu, rs, 2);
            l_i[hh] = l_i[hh] * sc + rs;
        }
        __syncwarp();   // Ps rows are private to this warp; order STS before LDS

        // ---- O += P V ----
        const float* Pb = Ps + (wid * 16) * 68;
#pragma unroll
        for (int ks = 0; ks < 8; ks++) {
            const int k0 = ks * 8;
            uint32_t pa[4];
            pa[0] = __float_as_uint(Pb[(g    ) * 68 + k0 + q]);
            pa[1] = __float_as_uint(Pb[(g + 8) * 68 + k0 + q]);
            pa[2] = __float_as_uint(Pb[(g    ) * 68 + k0 + q + 4]);
            pa[3] = __float_as_uint(Pb[(g + 8) * 68 + k0 + q + 4]);
#pragma unroll
            for (int nt = 0; nt < 8; nt++) {
                uint32_t bf[2];
                bf[0] = __float_as_uint(Vt[(nt * 8 + g) * 68 + k0 + q]);
                bf[1] = __float_as_uint(Vt[(nt * 8 + g) * 68 + k0 + q + 4]);
                mma8(o[nt], pa, bf);
            }
        }
    }

    // ---- normalize + write [S,B,E] for the output GEMM ----
#pragma unroll
    for (int hh = 0; hh < 2; hh++) {
        const float inv = 1.0f / l_i[hh];
        const int srow = qt * 128 + wid * 16 + g + hh * 8;
        float* dst = g_attn + ((size_t)srow * BATCH + b) * EMB + head * HDIM + 2 * q;
#pragma unroll
        for (int nt = 0; nt < 8; nt++) {
            float2 r2;
            r2.x = o[nt][hh * 2] * inv;
            r2.y = o[nt][hh * 2 + 1] * inv;
            *(float2*)(dst + nt * 8) = r2;
        }
    }
}

extern "C" void kernel_launch(void* const* d_in, const int* in_sizes, int n_in,
                              void* d_out, int out_size)
{
    const float* query         = (const float*)d_in[0];
    const float* amask         = (const float*)d_in[1];
    const unsigned char* pmask = (const unsigned char*)d_in[2];
    const float* W_in          = (const float*)d_in[3];
    const float* b_in          = (const float*)d_in[4];
    const float* W_out         = (const float*)d_in[5];
    const float* b_out         = (const float*)d_in[6];
    float* out = (float*)d_out;
    (void)in_sizes; (void)n_in; (void)out_size;

    cudaFuncSetAttribute(attn_tf32, cudaFuncAttributeMaxDynamicSharedMemorySize, 69632);

    // 1) QKV projection (tf32 mma) with fused routing + q scaling
    gemm_tf32<0><<<dim3(24, 64), 256>>>(query, W_in, b_in, nullptr);
    // 2) flash attention (tf32 mma)
    attn_tf32<<<dim3(16, 64), 256, 69632>>>(amask, pmask);
    // 3) output projection (tf32 mma)
    gemm_tf32<1><<<dim3(8, 64), 256>>>(nullptr, W_out, b_out, out);
}

// round 4
// speedup vs baseline: 2.2431x; 1.1386x over previous
#include <cuda_runtime.h>
#include <cstdint>

#define SEQ 2048
#define BATCH 4
#define EMB 1024
#define NHEAD 16
#define HDIM 64

// scratch (static device arrays: allocation-free rule)
__device__ float g_q[BATCH*NHEAD*SEQ*HDIM];
__device__ float g_k[BATCH*NHEAD*SEQ*HDIM];
__device__ float g_v[BATCH*NHEAD*SEQ*HDIM];
__device__ float g_attn[SEQ*BATCH*EMB];

// round-to-nearest tf32
__device__ __forceinline__ uint32_t f2tf(float x) {
    uint32_t r;
    asm("cvt.rna.tf32.f32 %0, %1;" : "=r"(r) : "f"(x));
    return r;
}

// m16n8k8 row.col tf32 mma, fp32 accumulate in place
__device__ __forceinline__ void mma8(float* c, const uint32_t* a, const uint32_t* b) {
    asm volatile(
        "mma.sync.aligned.m16n8k8.row.col.f32.tf32.tf32.f32 "
        "{%0,%1,%2,%3}, {%4,%5,%6,%7}, {%8,%9}, {%0,%1,%2,%3};"
        : "+f"(c[0]), "+f"(c[1]), "+f"(c[2]), "+f"(c[3])
        : "r"(a[0]), "r"(a[1]), "r"(a[2]), "r"(a[3]), "r"(b[0]), "r"(b[1]));
}

// fast exp on the FMA pipe; valid for x <= 0
__device__ __forceinline__ float fexp(float x) {
    float y = x * 1.4426950408889634f;
    y = fmaxf(y, -120.0f);
    float t = y + 12582912.0f;
    float nf = t - 12582912.0f;
    float f = y - nf;
    int n = __float_as_int(t) - 0x4B400000;
    float p =      1.3333558146e-3f;
    p = fmaf(p, f, 9.6181291076e-3f);
    p = fmaf(p, f, 5.5504108664e-2f);
    p = fmaf(p, f, 2.4022650696e-1f);
    p = fmaf(p, f, 6.9314718056e-1f);
    p = fmaf(p, f, 1.0f);
    return p * __int_as_float((n + 127) << 23);
}

// ---- cp.async helpers ----
__device__ __forceinline__ void cp16(uint32_t dst, const void* src) {
    asm volatile("cp.async.cg.shared.global [%0], [%1], 16;" :: "r"(dst), "l"(src));
}
__device__ __forceinline__ void cp_commit() {
    asm volatile("cp.async.commit_group;" ::: "memory");
}
__device__ __forceinline__ void cp_wait1() {
    asm volatile("cp.async.wait_group 1;" ::: "memory");
}

// C[M,N] = A[M,K] @ W[N,K]^T (+bias). 128x128 tile, BK=32, tf32 mma,
// cp.async double-buffered smem, cvt at fragment load.
// MODE 0: A=query, epilogue routes qkv -> g_q/g_k/g_v [B,H,S,D], scales q.
// MODE 1: A=g_attn, epilogue to out.
template<int MODE>
__global__ void __launch_bounds__(256)
gemm_tf32(const float* __restrict__ Ain, const float* __restrict__ W,
          const float* __restrict__ bias, float* __restrict__ out)
{
    extern __shared__ float sm[];
    // layout (floats): A stages [2][128][36] at 0, B stages at 9216
    const int ASTG = 128 * 36;              // 4608 floats per stage

    const int t    = threadIdx.x;
    const int lane = t & 31, g = lane >> 2, q = lane & 3;
    const int wid  = t >> 5, wm = wid >> 1, wn = wid & 1;
    const int m0   = blockIdx.y * 128;
    const int n0   = blockIdx.x * 128;

    const float* A = (MODE == 0) ? Ain : (const float*)g_attn;

    // loader: row = t>>1 (0..127), half = t&1 -> 16-float half of the 32-float row
    const int lrow = t >> 1;
    const int lh   = (t & 1) * 16;
    const float* Asrc = A + (size_t)(m0 + lrow) * EMB + lh;
    const float* Wsrc = W + (size_t)(n0 + lrow) * EMB + lh;
    const uint32_t adst0 = (uint32_t)__cvta_generic_to_shared(sm + lrow * 36 + lh);
    const uint32_t bdst0 = (uint32_t)__cvta_generic_to_shared(sm + 2 * ASTG + lrow * 36 + lh);
    const uint32_t SSTB  = ASTG * 4;        // stage stride in bytes

    float c[2][8][4];
#pragma unroll
    for (int mt = 0; mt < 2; mt++)
#pragma unroll
        for (int nt = 0; nt < 8; nt++)
#pragma unroll
            for (int r = 0; r < 4; r++) c[mt][nt][r] = 0.f;

    // prologue: stage 0
#pragma unroll
    for (int i = 0; i < 4; i++) {
        cp16(adst0 + i * 16, Asrc + i * 4);
        cp16(bdst0 + i * 16, Wsrc + i * 4);
    }
    cp_commit();

    int st = 0;
    for (int kb = 0; kb < EMB; kb += 32, st ^= 1) {
        if (kb + 32 < EMB) {
            const uint32_t so = (uint32_t)(st ^ 1) * SSTB;
#pragma unroll
            for (int i = 0; i < 4; i++) {
                cp16(adst0 + so + i * 16, Asrc + kb + 32 + i * 4);
                cp16(bdst0 + so + i * 16, Wsrc + kb + 32 + i * 4);
            }
        }
        cp_commit();
        cp_wait1();
        __syncthreads();

        const float* Ast = sm + st * ASTG;
        const float* Bst = sm + 2 * ASTG + st * ASTG;
#pragma unroll
        for (int ks = 0; ks < 4; ks++) {
            const int k0 = ks * 8;
            uint32_t af[2][4], bf[8][2];
#pragma unroll
            for (int mt = 0; mt < 2; mt++) {
                const int mb = wm * 32 + mt * 16;
                af[mt][0] = f2tf(Ast[(mb + g    ) * 36 + k0 + q]);
                af[mt][1] = f2tf(Ast[(mb + g + 8) * 36 + k0 + q]);
                af[mt][2] = f2tf(Ast[(mb + g    ) * 36 + k0 + q + 4]);
                af[mt][3] = f2tf(Ast[(mb + g + 8) * 36 + k0 + q + 4]);
            }
#pragma unroll
            for (int nt = 0; nt < 8; nt++) {
                const int nb = wn * 64 + nt * 8 + g;
                bf[nt][0] = f2tf(Bst[nb * 36 + k0 + q]);
                bf[nt][1] = f2tf(Bst[nb * 36 + k0 + q + 4]);
            }
#pragma unroll
            for (int mt = 0; mt < 2; mt++)
#pragma unroll
                for (int nt = 0; nt < 8; nt++)
                    mma8(c[mt][nt], af[mt], bf[nt]);
        }
        __syncthreads();
    }

#pragma unroll
    for (int mt = 0; mt < 2; mt++) {
#pragma unroll
        for (int nt = 0; nt < 8; nt++) {
#pragma unroll
            for (int r = 0; r < 4; r++) {
                const int m = m0 + wm * 32 + mt * 16 + g + ((r >= 2) ? 8 : 0);
                const int n = n0 + wn * 64 + nt * 8 + q * 2 + (r & 1);
                float v = c[mt][nt][r] + bias[n];
                if (MODE == 0) {
                    const int s = m >> 2, b = m & 3;
                    const int which = n >> 10;
                    const int e = n & 1023;
                    const int h = e >> 6, d = e & 63;
                    float* dst = (which == 0) ? g_q : (which == 1) ? g_k : g_v;
                    if (which == 0) v *= 0.125f;   // D^-0.5
                    dst[(((b * NHEAD + h) * SEQ) + s) * HDIM + d] = v;
                } else {
                    out[(size_t)m * EMB + n] = v;
                }
            }
        }
    }
}

// Flash attention, tf32 mma, cp.async double-buffered K/V tiles.
// Block: 128 q-rows of one (b,h), 256 threads; warp owns 16 q-rows; k-tiles of 64.
// K smem stride 68 (row-by-g reads: banks 4g+q), V stride 72 (row-by-q reads: 8q+g).
__global__ void __launch_bounds__(256)
attn_tf32(const float* __restrict__ mask, const unsigned char* __restrict__ pad)
{
    extern __shared__ float sm[];
    const int SK = 64 * 68;                  // 4352 floats / K stage
    const int SV = 64 * 72;                  // 4608 floats / V stage
    float* KsB = sm;                         // [2][64][68]
    float* VsB = sm + 2 * SK;                // [2][64][72]
    float* Ps  = sm + 2 * SK + 2 * SV;       // [128][68]

    const int t = threadIdx.x, lane = t & 31, g = lane >> 2, q = lane & 3;
    const int wid = t >> 5;
    const int qt = blockIdx.x;               // 0..15
    const int bh = blockIdx.y;               // 0..63
    const int b = bh >> 4, head = bh & 15;

    const float* Qg = g_q + (size_t)bh * SEQ * HDIM;
    const float* Kg = g_k + (size_t)bh * SEQ * HDIM;
    const float* Vg = g_v + (size_t)bh * SEQ * HDIM;
    const float* Mg = mask + (size_t)b * SEQ * SEQ + (size_t)(qt * 128) * SEQ;
    const unsigned char* Pg = pad + b * SEQ;

    // loader mapping: row = t>>2 (0..63), 4 x 16B segs starting at seg base (t&3)*4
    const int lr = t >> 2;
    const int lsf = (t & 3) * 16;            // starting float within 64-float row
    const float* Ksrc = Kg + (size_t)lr * HDIM + lsf;
    const float* Vsrc = Vg + (size_t)lr * HDIM + lsf;
    const uint32_t kdst0 = (uint32_t)__cvta_generic_to_shared(KsB + lr * 68 + lsf);
    const uint32_t vdst0 = (uint32_t)__cvta_generic_to_shared(VsB + lr * 72 + lsf);

    // Q fragments for this warp's 16 rows (registers, reused across all k-tiles)
    uint32_t qf[8][4];
    {
        const int r0 = qt * 128 + wid * 16;
#pragma unroll
        for (int ks = 0; ks < 8; ks++) {
            const int k0 = ks * 8;
            qf[ks][0] = f2tf(Qg[(size_t)(r0 + g    ) * HDIM + k0 + q]);
            qf[ks][1] = f2tf(Qg[(size_t)(r0 + g + 8) * HDIM + k0 + q]);
            qf[ks][2] = f2tf(Qg[(size_t)(r0 + g    ) * HDIM + k0 + q + 4]);
            qf[ks][3] = f2tf(Qg[(size_t)(r0 + g + 8) * HDIM + k0 + q + 4]);
        }
    }

    float o[8][4];
#pragma unroll
    for (int nt = 0; nt < 8; nt++)
#pragma unroll
        for (int r = 0; r < 4; r++) o[nt][r] = 0.f;
    float m_i[2] = {-1e30f, -1e30f};
    float l_i[2] = {0.f, 0.f};

    // prologue: stage 0 (kt=0)
#pragma unroll
    for (int i = 0; i < 4; i++) {
        cp16(kdst0 + i * 16, Ksrc + i * 4);
        cp16(vdst0 + i * 16, Vsrc + i * 4);
    }
    cp_commit();

    int st = 0;
    for (int kt = 0; kt < SEQ / 64; kt++, st ^= 1) {
        if (kt + 1 < SEQ / 64) {
            const uint32_t ko = (uint32_t)(st ^ 1) * (SK * 4);
            const uint32_t vo = (uint32_t)(st ^ 1) * (SV * 4);
            const size_t goff = (size_t)(kt + 1) * 64 * HDIM;
#pragma unroll
            for (int i = 0; i < 4; i++) {
                cp16(kdst0 + ko + i * 16, Ksrc + goff + i * 4);
                cp16(vdst0 + vo + i * 16, Vsrc + goff + i * 4);
            }
        }
        cp_commit();
        cp_wait1();
        __syncthreads();

        const float* Ks = KsB + st * SK;
        const float* Vs = VsB + st * SV;

        // hoist mask + padding loads (overlap with QK^T mma)
        float2 mk[2][8];
        uchar2 pd[8];
        const int kg0 = kt * 64 + 2 * q;
#pragma unroll
        for (int nt = 0; nt < 8; nt++) {
            pd[nt] = *(const uchar2*)(Pg + kg0 + nt * 8);
            mk[0][nt] = *(const float2*)(Mg + (size_t)(wid * 16 + g    ) * SEQ + kg0 + nt * 8);
            mk[1][nt] = *(const float2*)(Mg + (size_t)(wid * 16 + g + 8) * SEQ + kg0 + nt * 8);
        }

        // ---- S = Q K^T ----
        float s[8][4];
#pragma unroll
        for (int nt = 0; nt < 8; nt++)
#pragma unroll
            for (int r = 0; r < 4; r++) s[nt][r] = 0.f;
#pragma unroll
        for (int ks = 0; ks < 8; ks++) {
            const int k0 = ks * 8;
#pragma unroll
            for (int nt = 0; nt < 8; nt++) {
                uint32_t bf[2];
                bf[0] = f2tf(Ks[(nt * 8 + g) * 68 + k0 + q]);
                bf[1] = f2tf(Ks[(nt * 8 + g) * 68 + k0 + q + 4]);
                mma8(s[nt], qf[ks], bf);
            }
        }

        // ---- mask + padding + online softmax ----
#pragma unroll
        for (int hh = 0; hh < 2; hh++) {
            const int row = wid * 16 + g + hh * 8;
            float mx = -1e30f;
#pragma unroll
            for (int nt = 0; nt < 8; nt++) {
                float v0 = pd[nt].x ? -10000.f : s[nt][hh * 2]     + mk[hh][nt].x;
                float v1 = pd[nt].y ? -10000.f : s[nt][hh * 2 + 1] + mk[hh][nt].y;
                s[nt][hh * 2]     = v0;
                s[nt][hh * 2 + 1] = v1;
                mx = fmaxf(mx, fmaxf(v0, v1));
            }
            mx = fmaxf(mx, __shfl_xor_sync(0xffffffffu, mx, 1));
            mx = fmaxf(mx, __shfl_xor_sync(0xffffffffu, mx, 2));
            const float mnew = fmaxf(m_i[hh], mx);
            const float sc = fexp(m_i[hh] - mnew);
            m_i[hh] = mnew;
            float rs = 0.f;
            float* Pw = Ps + row * 68 + 2 * q;
#pragma unroll
            for (int nt = 0; nt < 8; nt++) {
                float p0 = fexp(s[nt][hh * 2]     - mnew);
                float p1 = fexp(s[nt][hh * 2 + 1] - mnew);
                rs += p0 + p1;
                float2 stv;
                stv.x = __uint_as_float(f2tf(p0));
                stv.y = __uint_as_float(f2tf(p1));
                *(float2*)(Pw + nt * 8) = stv;
                o[nt][hh * 2]     *= sc;
                o[nt][hh * 2 + 1] *= sc;
            }
            rs += __shfl_xor_sync(0xffffffffu, rs, 1);
            rs += __shfl_xor_sync(0xffffffffu, rs, 2);
            l_i[hh] = l_i[hh] * sc + rs;
        }
        __syncwarp();   // Ps rows are warp-private; order STS before LDS

        // ---- O += P V  (V stored [c][d], B frag reads V[k0+q][nt*8+g]) ----
        const float* Pb = Ps + (wid * 16) * 68;
#pragma unroll
        for (int ks = 0; ks < 8; ks++) {
            const int k0 = ks * 8;
            uint32_t pa[4];
            pa[0] = __float_as_uint(Pb[(g    ) * 68 + k0 + q]);
            pa[1] = __float_as_uint(Pb[(g + 8) * 68 + k0 + q]);
            pa[2] = __float_as_uint(Pb[(g    ) * 68 + k0 + q + 4]);
            pa[3] = __float_as_uint(Pb[(g + 8) * 68 + k0 + q + 4]);
#pragma unroll
            for (int nt = 0; nt < 8; nt++) {
                uint32_t bf[2];
                bf[0] = f2tf(Vs[(k0 + q    ) * 72 + nt * 8 + g]);
                bf[1] = f2tf(Vs[(k0 + q + 4) * 72 + nt * 8 + g]);
                mma8(o[nt], pa, bf);
            }
        }
        __syncthreads();   // all warps done with this stage before it is overwritten
    }

    // ---- normalize + write [S,B,E] for the output GEMM ----
#pragma unroll
    for (int hh = 0; hh < 2; hh++) {
        const float inv = 1.0f / l_i[hh];
        const int srow = qt * 128 + wid * 16 + g + hh * 8;
        float* dst = g_attn + ((size_t)srow * BATCH + b) * EMB + head * HDIM + 2 * q;
#pragma unroll
        for (int nt = 0; nt < 8; nt++) {
            float2 r2;
            r2.x = o[nt][hh * 2] * inv;
            r2.y = o[nt][hh * 2 + 1] * inv;
            *(float2*)(dst + nt * 8) = r2;
        }
    }
}

extern "C" void kernel_launch(void* const* d_in, const int* in_sizes, int n_in,
                              void* d_out, int out_size)
{
    const float* query         = (const float*)d_in[0];
    const float* amask         = (const float*)d_in[1];
    const unsigned char* pmask = (const unsigned char*)d_in[2];
    const float* W_in          = (const float*)d_in[3];
    const float* b_in          = (const float*)d_in[4];
    const float* W_out         = (const float*)d_in[5];
    const float* b_out         = (const float*)d_in[6];
    float* out = (float*)d_out;
    (void)in_sizes; (void)n_in; (void)out_size;

    const int GEMM_SMEM = 4 * 128 * 36 * 4;                     // 73728 B
    const int ATTN_SMEM = (2 * 64 * 68 + 2 * 64 * 72 + 128 * 68) * 4;  // 106496 B
    cudaFuncSetAttribute(gemm_tf32<0>, cudaFuncAttributeMaxDynamicSharedMemorySize, GEMM_SMEM);
    cudaFuncSetAttribute(gemm_tf32<1>, cudaFuncAttributeMaxDynamicSharedMemorySize, GEMM_SMEM);
    cudaFuncSetAttribute(attn_tf32,    cudaFuncAttributeMaxDynamicSharedMemorySize, ATTN_SMEM);

    // 1) QKV projection (tf32 mma, cp.async pipeline), fused routing + q scaling
    gemm_tf32<0><<<dim3(24, 64), 256, GEMM_SMEM>>>(query, W_in, b_in, nullptr);
    // 2) flash attention (tf32 mma, cp.async pipeline)
    attn_tf32<<<dim3(16, 64), 256, ATTN_SMEM>>>(amask, pmask);
    // 3) output projection
    gemm_tf32<1><<<dim3(8, 64), 256, GEMM_SMEM>>>(nullptr, W_out, b_out, out);
}

// round 5
// speedup vs baseline: 2.3853x; 1.0634x over previous
#include <cuda_runtime.h>
#include <cstdint>

#define SEQ 2048
#define BATCH 4
#define EMB 1024
#define NHEAD 16
#define HDIM 64

// scratch (static device arrays: allocation-free rule)
__device__ float g_q[BATCH*NHEAD*SEQ*HDIM];
__device__ float g_k[BATCH*NHEAD*SEQ*HDIM];
__device__ float g_v[BATCH*NHEAD*SEQ*HDIM];
__device__ float g_attn[SEQ*BATCH*EMB];
// pre-rounded (tf32) copies of inputs
__device__ float g_qr  [SEQ*BATCH*EMB];
__device__ float g_winr[3*EMB*EMB];
__device__ float g_woutr[EMB*EMB];

// round-to-nearest tf32
__device__ __forceinline__ uint32_t f2tf(float x) {
    uint32_t r;
    asm("cvt.rna.tf32.f32 %0, %1;" : "=r"(r) : "f"(x));
    return r;
}
__device__ __forceinline__ float f2tff(float x) { return __uint_as_float(f2tf(x)); }

// m16n8k8 row.col tf32 mma, fp32 accumulate in place
__device__ __forceinline__ void mma8(float* c, const uint32_t* a, const uint32_t* b) {
    asm volatile(
        "mma.sync.aligned.m16n8k8.row.col.f32.tf32.tf32.f32 "
        "{%0,%1,%2,%3}, {%4,%5,%6,%7}, {%8,%9}, {%0,%1,%2,%3};"
        : "+f"(c[0]), "+f"(c[1]), "+f"(c[2]), "+f"(c[3])
        : "r"(a[0]), "r"(a[1]), "r"(a[2]), "r"(a[3]), "r"(b[0]), "r"(b[1]));
}

// fast exp on the FMA pipe; valid for x <= 0
__device__ __forceinline__ float fexp(float x) {
    float y = x * 1.4426950408889634f;
    y = fmaxf(y, -120.0f);
    float t = y + 12582912.0f;
    float nf = t - 12582912.0f;
    float f = y - nf;
    int n = __float_as_int(t) - 0x4B400000;
    float p =      1.3333558146e-3f;
    p = fmaf(p, f, 9.6181291076e-3f);
    p = fmaf(p, f, 5.5504108664e-2f);
    p = fmaf(p, f, 2.4022650696e-1f);
    p = fmaf(p, f, 6.9314718056e-1f);
    p = fmaf(p, f, 1.0f);
    return p * __int_as_float((n + 127) << 23);
}

// ---- cp.async helpers ----
__device__ __forceinline__ void cp16(uint32_t dst, const void* src) {
    asm volatile("cp.async.cg.shared.global [%0], [%1], 16;" :: "r"(dst), "l"(src));
}
__device__ __forceinline__ void cp_commit() {
    asm volatile("cp.async.commit_group;" ::: "memory");
}
__device__ __forceinline__ void cp_wait1() {
    asm volatile("cp.async.wait_group 1;" ::: "memory");
}

// elementwise tf32 rounding prepass (n multiple of 1024)
__global__ void __launch_bounds__(256)
cvt_tf32(const float* __restrict__ src, float* __restrict__ dst, int n)
{
    int i = (blockIdx.x * 256 + threadIdx.x) * 4;
    if (i >= n) return;
    float4 v = *(const float4*)(src + i);
    v.x = f2tff(v.x); v.y = f2tff(v.y); v.z = f2tff(v.z); v.w = f2tff(v.w);
    *(float4*)(dst + i) = v;
}

// C[M,N] = A[M,K] @ W[N,K]^T (+bias). 128x128 tile, BK=32, tf32 mma,
// cp.async double-buffered smem. Operands pre-rounded -> no cvt in mainloop.
// MODE 0: A=g_qr, epilogue routes qkv -> g_q/g_k/g_v [B,H,S,D] (tf32-rounded), scales q.
// MODE 1: A=g_attn (pre-rounded), epilogue to out (fp32).
template<int MODE>
__global__ void __launch_bounds__(256, 2)
gemm_tf32(const float* __restrict__ W,
          const float* __restrict__ bias, float* __restrict__ out)
{
    extern __shared__ float sm[];
    const int ASTG = 128 * 36;              // floats per stage

    const int t    = threadIdx.x;
    const int lane = t & 31, g = lane >> 2, q = lane & 3;
    const int wid  = t >> 5, wm = wid >> 1, wn = wid & 1;
    const int m0   = blockIdx.y * 128;
    const int n0   = blockIdx.x * 128;

    const float* A = (MODE == 0) ? (const float*)g_qr : (const float*)g_attn;

    const int lrow = t >> 1;
    const int lh   = (t & 1) * 16;
    const float* Asrc = A + (size_t)(m0 + lrow) * EMB + lh;
    const float* Wsrc = W + (size_t)(n0 + lrow) * EMB + lh;
    const uint32_t adst0 = (uint32_t)__cvta_generic_to_shared(sm + lrow * 36 + lh);
    const uint32_t bdst0 = (uint32_t)__cvta_generic_to_shared(sm + 2 * ASTG + lrow * 36 + lh);
    const uint32_t SSTB  = ASTG * 4;

    float c[2][8][4];
#pragma unroll
    for (int mt = 0; mt < 2; mt++)
#pragma unroll
        for (int nt = 0; nt < 8; nt++)
#pragma unroll
            for (int r = 0; r < 4; r++) c[mt][nt][r] = 0.f;

#pragma unroll
    for (int i = 0; i < 4; i++) {
        cp16(adst0 + i * 16, Asrc + i * 4);
        cp16(bdst0 + i * 16, Wsrc + i * 4);
    }
    cp_commit();

    int st = 0;
    for (int kb = 0; kb < EMB; kb += 32, st ^= 1) {
        if (kb + 32 < EMB) {
            const uint32_t so = (uint32_t)(st ^ 1) * SSTB;
#pragma unroll
            for (int i = 0; i < 4; i++) {
                cp16(adst0 + so + i * 16, Asrc + kb + 32 + i * 4);
                cp16(bdst0 + so + i * 16, Wsrc + kb + 32 + i * 4);
            }
        }
        cp_commit();
        cp_wait1();
        __syncthreads();

        const float* Ast = sm + st * ASTG;
        const float* Bst = sm + 2 * ASTG + st * ASTG;
#pragma unroll
        for (int ks = 0; ks < 4; ks++) {
            const int k0 = ks * 8;
            uint32_t af[2][4], bf[8][2];
#pragma unroll
            for (int mt = 0; mt < 2; mt++) {
                const int mb = wm * 32 + mt * 16;
                af[mt][0] = __float_as_uint(Ast[(mb + g    ) * 36 + k0 + q]);
                af[mt][1] = __float_as_uint(Ast[(mb + g + 8) * 36 + k0 + q]);
                af[mt][2] = __float_as_uint(Ast[(mb + g    ) * 36 + k0 + q + 4]);
                af[mt][3] = __float_as_uint(Ast[(mb + g + 8) * 36 + k0 + q + 4]);
            }
#pragma unroll
            for (int nt = 0; nt < 8; nt++) {
                const int nb = wn * 64 + nt * 8 + g;
                bf[nt][0] = __float_as_uint(Bst[nb * 36 + k0 + q]);
                bf[nt][1] = __float_as_uint(Bst[nb * 36 + k0 + q + 4]);
            }
#pragma unroll
            for (int mt = 0; mt < 2; mt++)
#pragma unroll
                for (int nt = 0; nt < 8; nt++)
                    mma8(c[mt][nt], af[mt], bf[nt]);
        }
        __syncthreads();
    }

#pragma unroll
    for (int mt = 0; mt < 2; mt++) {
#pragma unroll
        for (int nt = 0; nt < 8; nt++) {
#pragma unroll
            for (int r = 0; r < 4; r++) {
                const int m = m0 + wm * 32 + mt * 16 + g + ((r >= 2) ? 8 : 0);
                const int n = n0 + wn * 64 + nt * 8 + q * 2 + (r & 1);
                float v = c[mt][nt][r] + bias[n];
                if (MODE == 0) {
                    const int s = m >> 2, b = m & 3;
                    const int which = n >> 10;
                    const int e = n & 1023;
                    const int h = e >> 6, d = e & 63;
                    float* dst = (which == 0) ? g_q : (which == 1) ? g_k : g_v;
                    if (which == 0) v *= 0.125f;   // D^-0.5
                    // pre-round: attention consumes these as tf32 mma operands
                    dst[(((b * NHEAD + h) * SEQ) + s) * HDIM + d] = f2tff(v);
                } else {
                    out[(size_t)m * EMB + n] = v;
                }
            }
        }
    }
}

// Flash attention, tf32 mma, cp.async double-buffered K/V tiles, 2 CTAs/SM.
// Block: 128 q-rows of one (b,h), 256 threads; warp owns 16 q-rows; k-tiles of 64.
// K smem stride 68 (reads by g: banks 4g+q), V stride 72 (reads by q: 8q+g).
__global__ void __launch_bounds__(256, 2)
attn_tf32(const float* __restrict__ mask, const unsigned char* __restrict__ pad)
{
    extern __shared__ float sm[];
    const int SK = 64 * 68;
    const int SV = 64 * 72;
    float* KsB = sm;                         // [2][64][68]
    float* VsB = sm + 2 * SK;                // [2][64][72]
    float* Ps  = sm + 2 * SK + 2 * SV;       // [128][68]

    const int t = threadIdx.x, lane = t & 31, g = lane >> 2, q = lane & 3;
    const int wid = t >> 5;
    const int qt = blockIdx.x;
    const int bh = blockIdx.y;
    const int b = bh >> 4, head = bh & 15;

    const float* Qg = g_q + (size_t)bh * SEQ * HDIM;
    const float* Kg = g_k + (size_t)bh * SEQ * HDIM;
    const float* Vg = g_v + (size_t)bh * SEQ * HDIM;
    const float* Mg = mask + (size_t)b * SEQ * SEQ + (size_t)(qt * 128) * SEQ;
    const unsigned char* Pg = pad + b * SEQ;

    const int lr = t >> 2;
    const int lsf = (t & 3) * 16;
    const float* Ksrc = Kg + (size_t)lr * HDIM + lsf;
    const float* Vsrc = Vg + (size_t)lr * HDIM + lsf;
    const uint32_t kdst0 = (uint32_t)__cvta_generic_to_shared(KsB + lr * 68 + lsf);
    const uint32_t vdst0 = (uint32_t)__cvta_generic_to_shared(VsB + lr * 72 + lsf);

    // Q fragments (pre-rounded in gmem; straight bit loads)
    uint32_t qf[8][4];
    {
        const int r0 = qt * 128 + wid * 16;
#pragma unroll
        for (int ks = 0; ks < 8; ks++) {
            const int k0 = ks * 8;
            qf[ks][0] = __float_as_uint(Qg[(size_t)(r0 + g    ) * HDIM + k0 + q]);
            qf[ks][1] = __float_as_uint(Qg[(size_t)(r0 + g + 8) * HDIM + k0 + q]);
            qf[ks][2] = __float_as_uint(Qg[(size_t)(r0 + g    ) * HDIM + k0 + q + 4]);
            qf[ks][3] = __float_as_uint(Qg[(size_t)(r0 + g + 8) * HDIM + k0 + q + 4]);
        }
    }

    float o[8][4];
#pragma unroll
    for (int nt = 0; nt < 8; nt++)
#pragma unroll
        for (int r = 0; r < 4; r++) o[nt][r] = 0.f;
    float m_i[2] = {-1e30f, -1e30f};
    float l_i[2] = {0.f, 0.f};

#pragma unroll
    for (int i = 0; i < 4; i++) {
        cp16(kdst0 + i * 16, Ksrc + i * 4);
        cp16(vdst0 + i * 16, Vsrc + i * 4);
    }
    cp_commit();

    int st = 0;
    for (int kt = 0; kt < SEQ / 64; kt++, st ^= 1) {
        if (kt + 1 < SEQ / 64) {
            const uint32_t ko = (uint32_t)(st ^ 1) * (SK * 4);
            const uint32_t vo = (uint32_t)(st ^ 1) * (SV * 4);
            const size_t goff = (size_t)(kt + 1) * 64 * HDIM;
#pragma unroll
            for (int i = 0; i < 4; i++) {
                cp16(kdst0 + ko + i * 16, Ksrc + goff + i * 4);
                cp16(vdst0 + vo + i * 16, Vsrc + goff + i * 4);
            }
        }
        cp_commit();
        cp_wait1();
        __syncthreads();

        const float* Ks = KsB + st * SK;
        const float* Vs = VsB + st * SV;

        // ---- S = Q K^T ----
        float s[8][4];
#pragma unroll
        for (int nt = 0; nt < 8; nt++)
#pragma unroll
            for (int r = 0; r < 4; r++) s[nt][r] = 0.f;
#pragma unroll
        for (int ks = 0; ks < 8; ks++) {
            const int k0 = ks * 8;
#pragma unroll
            for (int nt = 0; nt < 8; nt++) {
                uint32_t bf[2];
                bf[0] = __float_as_uint(Ks[(nt * 8 + g) * 68 + k0 + q]);
                bf[1] = __float_as_uint(Ks[(nt * 8 + g) * 68 + k0 + q + 4]);
                mma8(s[nt], qf[ks], bf);
            }
        }

        // ---- mask + padding + online softmax ----
        const int kg0 = kt * 64 + 2 * q;
#pragma unroll
        for (int hh = 0; hh < 2; hh++) {
            const int row = wid * 16 + g + hh * 8;
            const float* Mrow = Mg + (size_t)row * SEQ + kg0;
            const unsigned char* Prow = Pg + kg0;
            float mx = -1e30f;
#pragma unroll
            for (int nt = 0; nt < 8; nt++) {
                float2 mk = *(const float2*)(Mrow + nt * 8);
                uchar2 pd = *(const uchar2*)(Prow + nt * 8);
                float v0 = pd.x ? -10000.f : s[nt][hh * 2]     + mk.x;
                float v1 = pd.y ? -10000.f : s[nt][hh * 2 + 1] + mk.y;
                s[nt][hh * 2]     = v0;
                s[nt][hh * 2 + 1] = v1;
                mx = fmaxf(mx, fmaxf(v0, v1));
            }
            mx = fmaxf(mx, __shfl_xor_sync(0xffffffffu, mx, 1));
            mx = fmaxf(mx, __shfl_xor_sync(0xffffffffu, mx, 2));
            const float mnew = fmaxf(m_i[hh], mx);
            const float sc = fexp(m_i[hh] - mnew);
            m_i[hh] = mnew;
            float rs = 0.f;
            float* Pw = Ps + row * 68 + 2 * q;
#pragma unroll
            for (int nt = 0; nt < 8; nt++) {
                float p0 = fexp(s[nt][hh * 2]     - mnew);
                float p1 = fexp(s[nt][hh * 2 + 1] - mnew);
                rs += p0 + p1;
                float2 stv;
                stv.x = __uint_as_float(f2tf(p0));
                stv.y = __uint_as_float(f2tf(p1));
                *(float2*)(Pw + nt * 8) = stv;
                o[nt][hh * 2]     *= sc;
                o[nt][hh * 2 + 1] *= sc;
            }
            rs += __shfl_xor_sync(0xffffffffu, rs, 1);
            rs += __shfl_xor_sync(0xffffffffu, rs, 2);
            l_i[hh] = l_i[hh] * sc + rs;
        }
        __syncwarp();   // Ps rows are warp-private; order STS before LDS

        // ---- O += P V ----
        const float* Pb = Ps + (wid * 16) * 68;
#pragma unroll
        for (int ks = 0; ks < 8; ks++) {
            const int k0 = ks * 8;
            uint32_t pa[4];
            pa[0] = __float_as_uint(Pb[(g    ) * 68 + k0 + q]);
            pa[1] = __float_as_uint(Pb[(g + 8) * 68 + k0 + q]);
            pa[2] = __float_as_uint(Pb[(g    ) * 68 + k0 + q + 4]);
            pa[3] = __float_as_uint(Pb[(g + 8) * 68 + k0 + q + 4]);
#pragma unroll
            for (int nt = 0; nt < 8; nt++) {
                uint32_t bf[2];
                bf[0] = __float_as_uint(Vs[(k0 + q    ) * 72 + nt * 8 + g]);
                bf[1] = __float_as_uint(Vs[(k0 + q + 4) * 72 + nt * 8 + g]);
                mma8(o[nt], pa, bf);
            }
        }
        __syncthreads();
    }

    // ---- normalize + write [S,B,E] pre-rounded for the output GEMM ----
#pragma unroll
    for (int hh = 0; hh < 2; hh++) {
        const float inv = 1.0f / l_i[hh];
        const int srow = qt * 128 + wid * 16 + g + hh * 8;
        float* dst = g_attn + ((size_t)srow * BATCH + b) * EMB + head * HDIM + 2 * q;
#pragma unroll
        for (int nt = 0; nt < 8; nt++) {
            float2 r2;
            r2.x = f2tff(o[nt][hh * 2]     * inv);
            r2.y = f2tff(o[nt][hh * 2 + 1] * inv);
            *(float2*)(dst + nt * 8) = r2;
        }
    }
}

extern "C" void kernel_launch(void* const* d_in, const int* in_sizes, int n_in,
                              void* d_out, int out_size)
{
    const float* query         = (const float*)d_in[0];
    const float* amask         = (const float*)d_in[1];
    const unsigned char* pmask = (const unsigned char*)d_in[2];
    const float* W_in          = (const float*)d_in[3];
    const float* b_in          = (const float*)d_in[4];
    const float* W_out         = (const float*)d_in[5];
    const float* b_out         = (const float*)d_in[6];
    float* out = (float*)d_out;
    (void)in_sizes; (void)n_in; (void)out_size;

    const int GEMM_SMEM = 4 * 128 * 36 * 4;                            // 73728 B
    const int ATTN_SMEM = (2 * 64 * 68 + 2 * 64 * 72 + 128 * 68) * 4;  // 106496 B
    cudaFuncSetAttribute(gemm_tf32<0>, cudaFuncAttributeMaxDynamicSharedMemorySize, GEMM_SMEM);
    cudaFuncSetAttribute(gemm_tf32<1>, cudaFuncAttributeMaxDynamicSharedMemorySize, GEMM_SMEM);
    cudaFuncSetAttribute(attn_tf32,    cudaFuncAttributeMaxDynamicSharedMemorySize, ATTN_SMEM);

    float* d_qr; float* d_winr; float* d_woutr;
    cudaGetSymbolAddress((void**)&d_qr,   g_qr);
    cudaGetSymbolAddress((void**)&d_winr, g_winr);
    cudaGetSymbolAddress((void**)&d_woutr, g_woutr);

    // 0) tf32 rounding prepass (pure HBM, ~17us)
    cvt_tf32<<<SEQ*BATCH*EMB/1024, 256>>>(query, d_qr,   SEQ*BATCH*EMB);
    cvt_tf32<<<3*EMB*EMB/1024,     256>>>(W_in,  d_winr, 3*EMB*EMB);
    cvt_tf32<<<EMB*EMB/1024,       256>>>(W_out, d_woutr, EMB*EMB);

    // 1) QKV projection, fused routing + q scaling + tf32 rounding
    gemm_tf32<0><<<dim3(24, 64), 256, GEMM_SMEM>>>(d_winr, b_in, nullptr);
    // 2) flash attention
    attn_tf32<<<dim3(16, 64), 256, ATTN_SMEM>>>(amask, pmask);
    // 3) output projection
    gemm_tf32<1><<<dim3(8, 64), 256, GEMM_SMEM>>>(d_woutr, b_out, out);
}

// round 6
// speedup vs baseline: 3.8681x; 1.6216x over previous
#include <cuda_runtime.h>
#include <cuda_fp16.h>
#include <cstdint>

#define SEQ 2048
#define BATCH 4
#define EMB 1024
#define NHEAD 16
#define HDIM 64

// scratch (static device arrays: allocation-free rule) — all fp16
__device__ __half g_q[BATCH*NHEAD*SEQ*HDIM];
__device__ __half g_k[BATCH*NHEAD*SEQ*HDIM];
__device__ __half g_v[BATCH*NHEAD*SEQ*HDIM];
__device__ __half g_attn[SEQ*BATCH*EMB];
__device__ __half g_qr [SEQ*BATCH*EMB];
__device__ __half g_winr[3*EMB*EMB];
__device__ __half g_woutr[EMB*EMB];

// ---- mma / ldmatrix helpers ----
__device__ __forceinline__ void mma16(float* c, const uint32_t* a, const uint32_t* b) {
    asm volatile(
        "mma.sync.aligned.m16n8k16.row.col.f32.f16.f16.f32 "
        "{%0,%1,%2,%3}, {%4,%5,%6,%7}, {%8,%9}, {%0,%1,%2,%3};"
        : "+f"(c[0]), "+f"(c[1]), "+f"(c[2]), "+f"(c[3])
        : "r"(a[0]), "r"(a[1]), "r"(a[2]), "r"(a[3]), "r"(b[0]), "r"(b[1]));
}
__device__ __forceinline__ void ldsm4(uint32_t* r, uint32_t addr) {
    asm volatile("ldmatrix.sync.aligned.m8n8.x4.shared.b16 {%0,%1,%2,%3}, [%4];"
        : "=r"(r[0]), "=r"(r[1]), "=r"(r[2]), "=r"(r[3]) : "r"(addr));
}
__device__ __forceinline__ void ldsm4t(uint32_t* r, uint32_t addr) {
    asm volatile("ldmatrix.sync.aligned.m8n8.x4.trans.shared.b16 {%0,%1,%2,%3}, [%4];"
        : "=r"(r[0]), "=r"(r[1]), "=r"(r[2]), "=r"(r[3]) : "r"(addr));
}

// fast exp on the FMA pipe; valid for x <= 0
__device__ __forceinline__ float fexp(float x) {
    float y = x * 1.4426950408889634f;
    y = fmaxf(y, -120.0f);
    float t = y + 12582912.0f;
    float nf = t - 12582912.0f;
    float f = y - nf;
    int n = __float_as_int(t) - 0x4B400000;
    float p =      1.3333558146e-3f;
    p = fmaf(p, f, 9.6181291076e-3f);
    p = fmaf(p, f, 5.5504108664e-2f);
    p = fmaf(p, f, 2.4022650696e-1f);
    p = fmaf(p, f, 6.9314718056e-1f);
    p = fmaf(p, f, 1.0f);
    return p * __int_as_float((n + 127) << 23);
}

// ---- cp.async helpers ----
__device__ __forceinline__ void cp16(uint32_t dst, const void* src) {
    asm volatile("cp.async.cg.shared.global [%0], [%1], 16;" :: "r"(dst), "l"(src));
}
__device__ __forceinline__ void cp_commit() {
    asm volatile("cp.async.commit_group;" ::: "memory");
}
__device__ __forceinline__ void cp_wait1() {
    asm volatile("cp.async.wait_group 1;" ::: "memory");
}

// fp32 -> fp16 prepass (n multiple of 1024)
__global__ void __launch_bounds__(256)
cvt_fp16(const float* __restrict__ src, __half* __restrict__ dst, int n)
{
    int i = (blockIdx.x * 256 + threadIdx.x) * 4;
    if (i >= n) return;
    float4 v = *(const float4*)(src + i);
    __half2 h0 = __floats2half2_rn(v.x, v.y);
    __half2 h1 = __floats2half2_rn(v.z, v.w);
    *(__half2*)(dst + i)     = h0;
    *(__half2*)(dst + i + 2) = h1;
}

// C[M,N] = A[M,K] @ W[N,K]^T (+bias). 128x128 tile, BK=32, fp16 mma16816,
// ldmatrix fragments, cp.async double-buffered smem (rows stride 40 halves).
// MODE 0: A=g_qr, epilogue routes qkv -> g_q/g_k/g_v [B,H,S,D] fp16, scales q.
// MODE 1: A=g_attn, epilogue to out (fp32).
template<int MODE>
__global__ void __launch_bounds__(256, 2)
gemm_fp16(const __half* __restrict__ W,
          const float* __restrict__ bias, float* __restrict__ out)
{
    extern __shared__ __half hs[];
    const int LDA  = 40;                 // halves per row (80B: bank phase 20r, conflict-free)
    const int ASTG = 128 * LDA;          // halves per stage

    const int t    = threadIdx.x;
    const int lane = t & 31, g = lane >> 2, q = lane & 3;
    const int wid  = t >> 5, wm = wid >> 1, wn = wid & 1;
    const int m0   = blockIdx.y * 128;
    const int n0   = blockIdx.x * 128;
    const int ldmr = lane & 15, ldmc = (lane >> 4) * 8;

    const __half* A = (MODE == 0) ? (const __half*)g_qr : (const __half*)g_attn;

    const int lrow = t >> 1;
    const int lcol = (t & 1) * 16;
    const __half* Asrc = A + (size_t)(m0 + lrow) * EMB + lcol;
    const __half* Wsrc = W + (size_t)(n0 + lrow) * EMB + lcol;
    const uint32_t smem0 = (uint32_t)__cvta_generic_to_shared(hs);
    const uint32_t adst0 = smem0 + (lrow * LDA + lcol) * 2;
    const uint32_t bdst0 = smem0 + (2 * ASTG + lrow * LDA + lcol) * 2;
    const uint32_t SSTB  = ASTG * 2;     // stage stride bytes

    float c[2][8][4];
#pragma unroll
    for (int mt = 0; mt < 2; mt++)
#pragma unroll
        for (int nt = 0; nt < 8; nt++)
#pragma unroll
            for (int r = 0; r < 4; r++) c[mt][nt][r] = 0.f;

    // prologue: stage 0
    cp16(adst0,      Asrc);     cp16(adst0 + 16, Asrc + 8);
    cp16(bdst0,      Wsrc);     cp16(bdst0 + 16, Wsrc + 8);
    cp_commit();

    int st = 0;
    for (int kb = 0; kb < EMB; kb += 32, st ^= 1) {
        if (kb + 32 < EMB) {
            const uint32_t so = (uint32_t)(st ^ 1) * SSTB;
            cp16(adst0 + so,      Asrc + kb + 32);  cp16(adst0 + so + 16, Asrc + kb + 40);
            cp16(bdst0 + so,      Wsrc + kb + 32);  cp16(bdst0 + so + 16, Wsrc + kb + 40);
        }
        cp_commit();
        cp_wait1();
        __syncthreads();

        const uint32_t Ast = smem0 + st * SSTB;
        const uint32_t Bst = smem0 + 2 * ASTG * 2 + st * SSTB;
#pragma unroll
        for (int ks = 0; ks < 2; ks++) {
            uint32_t af[2][4];
#pragma unroll
            for (int mt = 0; mt < 2; mt++)
                ldsm4(af[mt], Ast + ((wm * 32 + mt * 16 + ldmr) * LDA + ks * 16 + ldmc) * 2);
            uint32_t bf[8][2];
#pragma unroll
            for (int n4 = 0; n4 < 4; n4++) {
                uint32_t tmp[4];
                ldsm4(tmp, Bst + ((wn * 64 + n4 * 16 + ldmr) * LDA + ks * 16 + ldmc) * 2);
                bf[n4 * 2][0]     = tmp[0]; bf[n4 * 2][1]     = tmp[2];
                bf[n4 * 2 + 1][0] = tmp[1]; bf[n4 * 2 + 1][1] = tmp[3];
            }
#pragma unroll
            for (int mt = 0; mt < 2; mt++)
#pragma unroll
                for (int nt = 0; nt < 8; nt++)
                    mma16(c[mt][nt], af[mt], bf[nt]);
        }
        __syncthreads();
    }

#pragma unroll
    for (int mt = 0; mt < 2; mt++) {
#pragma unroll
        for (int nt = 0; nt < 8; nt++) {
#pragma unroll
            for (int r = 0; r < 4; r++) {
                const int m = m0 + wm * 32 + mt * 16 + g + ((r >= 2) ? 8 : 0);
                const int n = n0 + wn * 64 + nt * 8 + q * 2 + (r & 1);
                float v = c[mt][nt][r] + bias[n];
                if (MODE == 0) {
                    const int s = m >> 2, b = m & 3;
                    const int which = n >> 10;
                    const int e = n & 1023;
                    const int h = e >> 6, d = e & 63;
                    __half* dst = (which == 0) ? g_q : (which == 1) ? g_k : g_v;
                    if (which == 0) v *= 0.125f;   // D^-0.5
                    dst[(((b * NHEAD + h) * SEQ) + s) * HDIM + d] = __float2half_rn(v);
                } else {
                    out[(size_t)m * EMB + n] = v;
                }
            }
        }
    }
}

// Flash attention, fp16 mma16816 + ldmatrix, cp.async double-buffered K/V.
// Block: 128 q-rows of one (b,h), 256 threads; warp owns 16 rows; kv-tiles of 64.
// All smem rows stride 72 halves (144B: bank phase 4r, conflict-free LDSM).
__global__ void __launch_bounds__(256, 2)
attn_fp16(const float* __restrict__ mask, const unsigned char* __restrict__ pad)
{
    extern __shared__ __half hs[];
    const int LD = 72;
    // halves layout: Qs[128][72] | KsB[2][64][72] | VsB[2][64][72] | Ps[128][72]
    __half* Ps_h = hs + 128 * LD + 4 * 64 * LD;

    const int t = threadIdx.x, lane = t & 31, g = lane >> 2, q = lane & 3;
    const int wid = t >> 5;
    const int qt = blockIdx.x;
    const int bh = blockIdx.y;
    const int b = bh >> 4, head = bh & 15;
    const int ldmr = lane & 15, ldmc = (lane >> 4) * 8;

    const __half* Qg = g_q + (size_t)bh * SEQ * HDIM;
    const __half* Kg = g_k + (size_t)bh * SEQ * HDIM;
    const __half* Vg = g_v + (size_t)bh * SEQ * HDIM;
    const float* Mg = mask + (size_t)b * SEQ * SEQ + (size_t)(qt * 128) * SEQ;
    const unsigned char* Pg = pad + b * SEQ;

    const uint32_t s0 = (uint32_t)__cvta_generic_to_shared(hs);
    const uint32_t Qb = s0;
    const uint32_t Kb = s0 + 128 * LD * 2;
    const uint32_t Vb = Kb + 2 * 64 * LD * 2;
    const uint32_t Pb = Vb + 2 * 64 * LD * 2;
    const uint32_t KVSTB = 64 * LD * 2;     // stage stride bytes

    // loaders
    const __half* Qsrc = Qg + (size_t)(qt * 128 + (t >> 1)) * HDIM + (t & 1) * 32;
    const uint32_t qdst = Qb + ((t >> 1) * LD + (t & 1) * 32) * 2;
    const __half* Ksrc = Kg + (size_t)(t >> 2) * HDIM + (t & 3) * 16;
    const __half* Vsrc = Vg + (size_t)(t >> 2) * HDIM + (t & 3) * 16;
    const uint32_t kdst0 = Kb + ((t >> 2) * LD + (t & 3) * 16) * 2;
    const uint32_t vdst0 = Vb + ((t >> 2) * LD + (t & 3) * 16) * 2;

    float o[8][4];
#pragma unroll
    for (int nt = 0; nt < 8; nt++)
#pragma unroll
        for (int r = 0; r < 4; r++) o[nt][r] = 0.f;
    float m_i[2] = {-1e30f, -1e30f};
    float l_i[2] = {0.f, 0.f};
    uint32_t qf[4][4];

    // prologue: Q tile + KV stage 0 in group 0
#pragma unroll
    for (int i = 0; i < 4; i++) cp16(qdst + i * 16, Qsrc + i * 8);
    cp16(kdst0,      Ksrc);     cp16(kdst0 + 16, Ksrc + 8);
    cp16(vdst0,      Vsrc);     cp16(vdst0 + 16, Vsrc + 8);
    cp_commit();

    int st = 0;
    for (int kt = 0; kt < SEQ / 64; kt++, st ^= 1) {
        if (kt + 1 < SEQ / 64) {
            const uint32_t so = (uint32_t)(st ^ 1) * KVSTB;
            const size_t goff = (size_t)(kt + 1) * 64 * HDIM;
            cp16(kdst0 + so,      Ksrc + goff);  cp16(kdst0 + so + 16, Ksrc + goff + 8);
            cp16(vdst0 + so,      Vsrc + goff);  cp16(vdst0 + so + 16, Vsrc + goff + 8);
        }
        cp_commit();
        cp_wait1();
        __syncthreads();

        if (kt == 0) {   // hoist Q fragments once (Q arrived with group 0)
#pragma unroll
            for (int ks = 0; ks < 4; ks++)
                ldsm4(qf[ks], Qb + ((wid * 16 + ldmr) * LD + ks * 16 + ldmc) * 2);
        }

        const uint32_t Kst = Kb + st * KVSTB;
        const uint32_t Vst = Vb + st * KVSTB;

        // ---- S = Q K^T ----
        float s[8][4];
#pragma unroll
        for (int nt = 0; nt < 8; nt++)
#pragma unroll
            for (int r = 0; r < 4; r++) s[nt][r] = 0.f;
#pragma unroll
        for (int ks = 0; ks < 4; ks++) {
            uint32_t bf[8][2];
#pragma unroll
            for (int n4 = 0; n4 < 4; n4++) {
                uint32_t tmp[4];
                ldsm4(tmp, Kst + ((n4 * 16 + ldmr) * LD + ks * 16 + ldmc) * 2);
                bf[n4 * 2][0]     = tmp[0]; bf[n4 * 2][1]     = tmp[2];
                bf[n4 * 2 + 1][0] = tmp[1]; bf[n4 * 2 + 1][1] = tmp[3];
            }
#pragma unroll
            for (int nt = 0; nt < 8; nt++)
                mma16(s[nt], qf[ks], bf[nt]);
        }

        // ---- mask + padding + online softmax ----
        const int kg0 = kt * 64 + 2 * q;
#pragma unroll
        for (int hh = 0; hh < 2; hh++) {
            const int row = wid * 16 + g + hh * 8;
            const float* Mrow = Mg + (size_t)row * SEQ + kg0;
            const unsigned char* Prow = Pg + kg0;
            float mx = -1e30f;
#pragma unroll
            for (int nt = 0; nt < 8; nt++) {
                float2 mk = *(const float2*)(Mrow + nt * 8);
                uchar2 pd = *(const uchar2*)(Prow + nt * 8);
                float v0 = pd.x ? -10000.f : s[nt][hh * 2]     + mk.x;
                float v1 = pd.y ? -10000.f : s[nt][hh * 2 + 1] + mk.y;
                s[nt][hh * 2]     = v0;
                s[nt][hh * 2 + 1] = v1;
                mx = fmaxf(mx, fmaxf(v0, v1));
            }
            mx = fmaxf(mx, __shfl_xor_sync(0xffffffffu, mx, 1));
            mx = fmaxf(mx, __shfl_xor_sync(0xffffffffu, mx, 2));
            const float mnew = fmaxf(m_i[hh], mx);
            const float sc = fexp(m_i[hh] - mnew);
            m_i[hh] = mnew;
            float rs = 0.f;
            __half* Pw = Ps_h + row * LD + 2 * q;
#pragma unroll
            for (int nt = 0; nt < 8; nt++) {
                float p0 = fexp(s[nt][hh * 2]     - mnew);
                float p1 = fexp(s[nt][hh * 2 + 1] - mnew);
                rs += p0 + p1;
                *(__half2*)(Pw + nt * 8) = __floats2half2_rn(p0, p1);
                o[nt][hh * 2]     *= sc;
                o[nt][hh * 2 + 1] *= sc;
            }
            rs += __shfl_xor_sync(0xffffffffu, rs, 1);
            rs += __shfl_xor_sync(0xffffffffu, rs, 2);
            l_i[hh] = l_i[hh] * sc + rs;
        }
        __syncwarp();   // Ps rows warp-private; order STS before LDSM

        // ---- O += P V  (A = Ps via ldmatrix, B = V via ldmatrix.trans) ----
#pragma unroll
        for (int ks = 0; ks < 4; ks++) {
            uint32_t pa[4];
            ldsm4(pa, Pb + ((wid * 16 + ldmr) * LD + ks * 16 + ldmc) * 2);
            uint32_t bf[8][2];
#pragma unroll
            for (int n4 = 0; n4 < 4; n4++) {
                uint32_t tmp[4];
                ldsm4t(tmp, Vst + ((ks * 16 + ldmr) * LD + n4 * 16 + ldmc) * 2);
                // trans mapping: m0=b0,m1=b1 of d-tile n4*2; m2=b0,m3=b1 of n4*2+1
                bf[n4 * 2][0]     = tmp[0]; bf[n4 * 2][1]     = tmp[1];
                bf[n4 * 2 + 1][0] = tmp[2]; bf[n4 * 2 + 1][1] = tmp[3];
            }
#pragma unroll
            for (int nt = 0; nt < 8; nt++)
                mma16(o[nt], pa, bf[nt]);
        }
        __syncthreads();   // all warps done with stage st before overwrite
    }

    // ---- normalize + write [S,B,E] fp16 for the output GEMM ----
#pragma unroll
    for (int hh = 0; hh < 2; hh++) {
        const float inv = 1.0f / l_i[hh];
        const int srow = qt * 128 + wid * 16 + g + hh * 8;
        __half* dst = g_attn + ((size_t)srow * BATCH + b) * EMB + head * HDIM + 2 * q;
#pragma unroll
        for (int nt = 0; nt < 8; nt++) {
            *(__half2*)(dst + nt * 8) =
                __floats2half2_rn(o[nt][hh * 2] * inv, o[nt][hh * 2 + 1] * inv);
        }
    }
}

extern "C" void kernel_launch(void* const* d_in, const int* in_sizes, int n_in,
                              void* d_out, int out_size)
{
    const float* query         = (const float*)d_in[0];
    const float* amask         = (const float*)d_in[1];
    const unsigned char* pmask = (const unsigned char*)d_in[2];
    const float* W_in          = (const float*)d_in[3];
    const float* b_in          = (const float*)d_in[4];
    const float* W_out         = (const float*)d_in[5];
    const float* b_out         = (const float*)d_in[6];
    float* out = (float*)d_out;
    (void)in_sizes; (void)n_in; (void)out_size;

    const int GEMM_SMEM = 4 * 128 * 40 * 2;                    // 40960 B
    const int ATTN_SMEM = (2 * 128 * 72 + 4 * 64 * 72) * 2;    // 73728 B
    cudaFuncSetAttribute(gemm_fp16<0>, cudaFuncAttributeMaxDynamicSharedMemorySize, GEMM_SMEM);
    cudaFuncSetAttribute(gemm_fp16<1>, cudaFuncAttributeMaxDynamicSharedMemorySize, GEMM_SMEM);
    cudaFuncSetAttribute(attn_fp16,    cudaFuncAttributeMaxDynamicSharedMemorySize, ATTN_SMEM);

    __half* d_qr; __half* d_winr; __half* d_woutr;
    cudaGetSymbolAddress((void**)&d_qr,    g_qr);
    cudaGetSymbolAddress((void**)&d_winr,  g_winr);
    cudaGetSymbolAddress((void**)&d_woutr, g_woutr);

    // 0) fp16 conversion prepass (pure HBM)
    cvt_fp16<<<SEQ*BATCH*EMB/1024, 256>>>(query, d_qr,    SEQ*BATCH*EMB);
    cvt_fp16<<<3*EMB*EMB/1024,     256>>>(W_in,  d_winr,  3*EMB*EMB);
    cvt_fp16<<<EMB*EMB/1024,       256>>>(W_out, d_woutr, EMB*EMB);

    // 1) QKV projection, fused routing + q scaling
    gemm_fp16<0><<<dim3(24, 64), 256, GEMM_SMEM>>>(d_winr, b_in, nullptr);
    // 2) flash attention
    attn_fp16<<<dim3(16, 64), 256, ATTN_SMEM>>>(amask, pmask);
    // 3) output projection
    gemm_fp16<1><<<dim3(8, 64), 256, GEMM_SMEM>>>(d_woutr, b_out, out);
}

// round 7
// speedup vs baseline: 5.1073x; 1.3204x over previous
#include <cuda_runtime.h>
#include <cuda_fp16.h>
#include <cstdint>

#define SEQ 2048
#define BATCH 4
#define EMB 1024
#define NHEAD 16
#define HDIM 64
#define LOG2E 1.4426950408889634f

// scratch (static device arrays: allocation-free rule)
__device__ __half g_q[BATCH*NHEAD*SEQ*HDIM];
__device__ __half g_k[BATCH*NHEAD*SEQ*HDIM];
__device__ __half g_v[BATCH*NHEAD*SEQ*HDIM];
__device__ __half g_attn[SEQ*BATCH*EMB];
__device__ __half g_qr [SEQ*BATCH*EMB];
__device__ __half g_winr[3*EMB*EMB];
__device__ __half g_woutr[EMB*EMB];
__device__ __half g_maskh[BATCH*SEQ*SEQ];   // pad-folded, pre-scaled by log2e

// ---- mma / ldmatrix helpers ----
__device__ __forceinline__ void mma16(float* c, const uint32_t* a, const uint32_t* b) {
    asm volatile(
        "mma.sync.aligned.m16n8k16.row.col.f32.f16.f16.f32 "
        "{%0,%1,%2,%3}, {%4,%5,%6,%7}, {%8,%9}, {%0,%1,%2,%3};"
        : "+f"(c[0]), "+f"(c[1]), "+f"(c[2]), "+f"(c[3])
        : "r"(a[0]), "r"(a[1]), "r"(a[2]), "r"(a[3]), "r"(b[0]), "r"(b[1]));
}
__device__ __forceinline__ void ldsm4(uint32_t* r, uint32_t addr) {
    asm volatile("ldmatrix.sync.aligned.m8n8.x4.shared.b16 {%0,%1,%2,%3}, [%4];"
        : "=r"(r[0]), "=r"(r[1]), "=r"(r[2]), "=r"(r[3]) : "r"(addr));
}
__device__ __forceinline__ void ldsm4t(uint32_t* r, uint32_t addr) {
    asm volatile("ldmatrix.sync.aligned.m8n8.x4.trans.shared.b16 {%0,%1,%2,%3}, [%4];"
        : "=r"(r[0]), "=r"(r[1]), "=r"(r[2]), "=r"(r[3]) : "r"(addr));
}

// fast exp2 on the FMA pipe; valid for x <= 0
__device__ __forceinline__ float fexp2(float x) {
    float y = fmaxf(x, -126.0f);
    float t = y + 12582912.0f;
    float f = y - (t - 12582912.0f);
    int n = __float_as_int(t) - 0x4B400000;
    float p =      1.3333558146e-3f;
    p = fmaf(p, f, 9.6181291076e-3f);
    p = fmaf(p, f, 5.5504108664e-2f);
    p = fmaf(p, f, 2.4022650696e-1f);
    p = fmaf(p, f, 6.9314718056e-1f);
    p = fmaf(p, f, 1.0f);
    return p * __int_as_float((n + 127) << 23);
}

// ---- cp.async helpers ----
__device__ __forceinline__ void cp16(uint32_t dst, const void* src) {
    asm volatile("cp.async.cg.shared.global [%0], [%1], 16;" :: "r"(dst), "l"(src));
}
__device__ __forceinline__ void cp_commit() {
    asm volatile("cp.async.commit_group;" ::: "memory");
}
__device__ __forceinline__ void cp_wait2() {
    asm volatile("cp.async.wait_group 2;" ::: "memory");
}

// fp32 -> fp16 prepass (n multiple of 1024)
__global__ void __launch_bounds__(256)
cvt_fp16(const float* __restrict__ src, __half* __restrict__ dst, int n)
{
    int i = (blockIdx.x * 256 + threadIdx.x) * 4;
    if (i >= n) return;
    float4 v = *(const float4*)(src + i);
    *(__half2*)(dst + i)     = __floats2half2_rn(v.x, v.y);
    *(__half2*)(dst + i + 2) = __floats2half2_rn(v.z, v.w);
}

// mask prepass: fold padding, pre-scale by log2e, store fp16
__global__ void __launch_bounds__(256)
prep_mask(const float* __restrict__ mask, const unsigned char* __restrict__ pad,
          __half* __restrict__ dst)
{
    int i = (blockIdx.x * 256 + threadIdx.x) * 4;
    int b = i / (SEQ * SEQ);
    int c = i & (SEQ - 1);
    float4 m = *(const float4*)(mask + i);
    const unsigned char* pb = pad + b * SEQ + c;
    float v0 = pb[0] ? -14427.0f : m.x * LOG2E;
    float v1 = pb[1] ? -14427.0f : m.y * LOG2E;
    float v2 = pb[2] ? -14427.0f : m.z * LOG2E;
    float v3 = pb[3] ? -14427.0f : m.w * LOG2E;
    *(__half2*)(dst + i)     = __floats2half2_rn(v0, v1);
    *(__half2*)(dst + i + 2) = __floats2half2_rn(v2, v3);
}

// C[M,N] = A[M,K] @ W[N,K]^T (+bias). 128x128 tile, BK=32, fp16 mma16816,
// 4-stage cp.async pipeline, one __syncthreads per slab.
// MODE 0: A=g_qr, routes qkv -> g_q/g_k/g_v [B,H,S,D] fp16, scales q by 0.125*log2e.
// MODE 1: A=g_attn, epilogue to out (fp32).
template<int MODE>
__global__ void __launch_bounds__(256, 2)
gemm_fp16(const __half* __restrict__ W,
          const float* __restrict__ bias, float* __restrict__ out)
{
    extern __shared__ __half hs[];
    const int LDA  = 40;                 // 80B rows: LDSM bank phase 20r, conflict-free
    const int ASTG = 128 * LDA;
    const int NST  = 4;
    const int NSLAB = EMB / 32;          // 32

    const int t    = threadIdx.x;
    const int lane = t & 31, g = lane >> 2, q = lane & 3;
    const int wid  = t >> 5, wm = wid >> 1, wn = wid & 1;
    const int m0   = blockIdx.y * 128;
    const int n0   = blockIdx.x * 128;
    const int ldmr = lane & 15, ldmc = (lane >> 4) * 8;

    const __half* A = (MODE == 0) ? (const __half*)g_qr : (const __half*)g_attn;
    const int lrow = t >> 1;
    const int lcol = (t & 1) * 16;
    const __half* Asrc = A + (size_t)(m0 + lrow) * EMB + lcol;
    const __half* Wsrc = W + (size_t)(n0 + lrow) * EMB + lcol;
    const uint32_t smem0 = (uint32_t)__cvta_generic_to_shared(hs);
    const uint32_t adst0 = smem0 + (lrow * LDA + lcol) * 2;
    const uint32_t bdst0 = smem0 + (NST * ASTG + lrow * LDA + lcol) * 2;
    const uint32_t SSTB  = ASTG * 2;

    float c[2][8][4];
#pragma unroll
    for (int mt = 0; mt < 2; mt++)
#pragma unroll
        for (int nt = 0; nt < 8; nt++)
#pragma unroll
            for (int r = 0; r < 4; r++) c[mt][nt][r] = 0.f;

    // prologue: slabs 0,1,2
#pragma unroll
    for (int s = 0; s < 3; s++) {
        const uint32_t so = (uint32_t)s * SSTB;
        cp16(adst0 + so,      Asrc + s * 32);  cp16(adst0 + so + 16, Asrc + s * 32 + 8);
        cp16(bdst0 + so,      Wsrc + s * 32);  cp16(bdst0 + so + 16, Wsrc + s * 32 + 8);
        cp_commit();
    }

    for (int i = 0; i < NSLAB; i++) {
        cp_wait2();
        __syncthreads();
        if (i + 3 < NSLAB) {
            const uint32_t so = (uint32_t)((i + 3) & 3) * SSTB;
            cp16(adst0 + so,      Asrc + (i + 3) * 32);  cp16(adst0 + so + 16, Asrc + (i + 3) * 32 + 8);
            cp16(bdst0 + so,      Wsrc + (i + 3) * 32);  cp16(bdst0 + so + 16, Wsrc + (i + 3) * 32 + 8);
        }
        cp_commit();

        const uint32_t Ast = smem0 + (uint32_t)(i & 3) * SSTB;
        const uint32_t Bst = smem0 + NST * SSTB + (uint32_t)(i & 3) * SSTB;
#pragma unroll
        for (int ks = 0; ks < 2; ks++) {
            uint32_t af[2][4];
#pragma unroll
            for (int mt = 0; mt < 2; mt++)
                ldsm4(af[mt], Ast + ((wm * 32 + mt * 16 + ldmr) * LDA + ks * 16 + ldmc) * 2);
            uint32_t bf[8][2];
#pragma unroll
            for (int n4 = 0; n4 < 4; n4++) {
                uint32_t tmp[4];
                ldsm4(tmp, Bst + ((wn * 64 + n4 * 16 + ldmr) * LDA + ks * 16 + ldmc) * 2);
                bf[n4 * 2][0]     = tmp[0]; bf[n4 * 2][1]     = tmp[2];
                bf[n4 * 2 + 1][0] = tmp[1]; bf[n4 * 2 + 1][1] = tmp[3];
            }
#pragma unroll
            for (int mt = 0; mt < 2; mt++)
#pragma unroll
                for (int nt = 0; nt < 8; nt++)
                    mma16(c[mt][nt], af[mt], bf[nt]);
        }
    }

#pragma unroll
    for (int mt = 0; mt < 2; mt++) {
#pragma unroll
        for (int nt = 0; nt < 8; nt++) {
#pragma unroll
            for (int r = 0; r < 4; r++) {
                const int m = m0 + wm * 32 + mt * 16 + g + ((r >= 2) ? 8 : 0);
                const int n = n0 + wn * 64 + nt * 8 + q * 2 + (r & 1);
                float v = c[mt][nt][r] + bias[n];
                if (MODE == 0) {
                    const int s = m >> 2, b = m & 3;
                    const int which = n >> 10;
                    const int e = n & 1023;
                    const int h = e >> 6, d = e & 63;
                    __half* dst = (which == 0) ? g_q : (which == 1) ? g_k : g_v;
                    if (which == 0) v *= 0.125f * LOG2E;   // D^-0.5 * log2e (exp2 domain)
                    dst[(((b * NHEAD + h) * SEQ) + s) * HDIM + d] = __float2half_rn(v);
                } else {
                    out[(size_t)m * EMB + n] = v;
                }
            }
        }
    }
}

// Flash attention, fp16 mma16816, P kept in registers (C-frag == A-frag trick),
// 4-stage cp.async KV pipeline, one __syncthreads per kv-tile, exp2-domain softmax.
__global__ void __launch_bounds__(256, 2)
attn_fp16()
{
    extern __shared__ __half hs[];
    const int LD  = 72;                 // 144B rows: LDSM bank phase 4r, conflict-free
    const int NST = 4;
    const int NKT = SEQ / 64;           // 32

    const int t = threadIdx.x, lane = t & 31, g = lane >> 2, q = lane & 3;
    const int wid = t >> 5;
    const int qt = blockIdx.x;
    const int bh = blockIdx.y;
    const int b = bh >> 4, head = bh & 15;
    const int ldmr = lane & 15, ldmc = (lane >> 4) * 8;

    const __half* Qg = g_q + (size_t)bh * SEQ * HDIM;
    const __half* Kg = g_k + (size_t)bh * SEQ * HDIM;
    const __half* Vg = g_v + (size_t)bh * SEQ * HDIM;
    const __half* Mg = g_maskh + (size_t)b * SEQ * SEQ + (size_t)(qt * 128) * SEQ;

    const uint32_t s0v = (uint32_t)__cvta_generic_to_shared(hs);
    const uint32_t Qb = s0v;                       // [128][72]
    const uint32_t Kb = s0v + 128 * LD * 2;        // [4][64][72]
    const uint32_t Vb = Kb + NST * 64 * LD * 2;    // [4][64][72]
    const uint32_t KVSTB = 64 * LD * 2;

    const __half* Qsrc = Qg + (size_t)(qt * 128 + (t >> 1)) * HDIM + (t & 1) * 32;
    const uint32_t qdst = Qb + ((t >> 1) * LD + (t & 1) * 32) * 2;
    const __half* Ksrc = Kg + (size_t)(t >> 2) * HDIM + (t & 3) * 16;
    const __half* Vsrc = Vg + (size_t)(t >> 2) * HDIM + (t & 3) * 16;
    const uint32_t kdst0 = Kb + ((t >> 2) * LD + (t & 3) * 16) * 2;
    const uint32_t vdst0 = Vb + ((t >> 2) * LD + (t & 3) * 16) * 2;

    float o[8][4];
#pragma unroll
    for (int nt = 0; nt < 8; nt++)
#pragma unroll
        for (int r = 0; r < 4; r++) o[nt][r] = 0.f;
    float m_i[2] = {-1e30f, -1e30f};
    float l_i[2] = {0.f, 0.f};
    uint32_t qf[4][4];

    // prologue: Q with kv-stage 0, then stages 1,2
#pragma unroll
    for (int i = 0; i < 4; i++) cp16(qdst + i * 16, Qsrc + i * 8);
#pragma unroll
    for (int s = 0; s < 3; s++) {
        const uint32_t so = (uint32_t)s * KVSTB;
        const size_t goff = (size_t)s * 64 * HDIM;
        cp16(kdst0 + so, Ksrc + goff);  cp16(kdst0 + so + 16, Ksrc + goff + 8);
        cp16(vdst0 + so, Vsrc + goff);  cp16(vdst0 + so + 16, Vsrc + goff + 8);
        cp_commit();
    }

    for (int kt = 0; kt < NKT; kt++) {
        cp_wait2();
        __syncthreads();

        if (kt == 0) {   // Q arrived with group 0
#pragma unroll
            for (int ks = 0; ks < 4; ks++)
                ldsm4(qf[ks], Qb + ((wid * 16 + ldmr) * LD + ks * 16 + ldmc) * 2);
        }
        if (kt + 3 < NKT) {
            const uint32_t so = (uint32_t)((kt + 3) & 3) * KVSTB;
            const size_t goff = (size_t)(kt + 3) * 64 * HDIM;
            cp16(kdst0 + so, Ksrc + goff);  cp16(kdst0 + so + 16, Ksrc + goff + 8);
            cp16(vdst0 + so, Vsrc + goff);  cp16(vdst0 + so + 16, Vsrc + goff + 8);
        }
        cp_commit();

        const uint32_t Kst = Kb + (uint32_t)(kt & 3) * KVSTB;
        const uint32_t Vst = Vb + (uint32_t)(kt & 3) * KVSTB;

        // ---- S = Q K^T (exp2-domain: Q pre-scaled by 0.125*log2e) ----
        float s[8][4];
#pragma unroll
        for (int nt = 0; nt < 8; nt++)
#pragma unroll
            for (int r = 0; r < 4; r++) s[nt][r] = 0.f;
#pragma unroll
        for (int ks = 0; ks < 4; ks++) {
            uint32_t bf[8][2];
#pragma unroll
            for (int n4 = 0; n4 < 4; n4++) {
                uint32_t tmp[4];
                ldsm4(tmp, Kst + ((n4 * 16 + ldmr) * LD + ks * 16 + ldmc) * 2);
                bf[n4 * 2][0]     = tmp[0]; bf[n4 * 2][1]     = tmp[2];
                bf[n4 * 2 + 1][0] = tmp[1]; bf[n4 * 2 + 1][1] = tmp[3];
            }
#pragma unroll
            for (int nt = 0; nt < 8; nt++)
                mma16(s[nt], qf[ks], bf[nt]);
        }

        // ---- mask (pad-folded fp16) + online softmax; pack P into A-frags ----
        uint32_t pa_lo[8], pa_hi[8];
        const int kg0 = kt * 64 + 2 * q;
#pragma unroll
        for (int hh = 0; hh < 2; hh++) {
            const int row = wid * 16 + g + hh * 8;
            const __half* Mrow = Mg + (size_t)row * SEQ + kg0;
            float mx = -1e30f;
#pragma unroll
            for (int nt = 0; nt < 8; nt++) {
                float2 mf = __half22float2(*(const __half2*)(Mrow + nt * 8));
                float v0 = s[nt][hh * 2]     + mf.x;
                float v1 = s[nt][hh * 2 + 1] + mf.y;
                s[nt][hh * 2]     = v0;
                s[nt][hh * 2 + 1] = v1;
                mx = fmaxf(mx, fmaxf(v0, v1));
            }
            mx = fmaxf(mx, __shfl_xor_sync(0xffffffffu, mx, 1));
            mx = fmaxf(mx, __shfl_xor_sync(0xffffffffu, mx, 2));
            const float mnew = fmaxf(m_i[hh], mx);
            const float sc = fexp2(m_i[hh] - mnew);
            m_i[hh] = mnew;
            float rs = 0.f;
#pragma unroll
            for (int nt = 0; nt < 8; nt++) {
                float p0 = fexp2(s[nt][hh * 2]     - mnew);
                float p1 = fexp2(s[nt][hh * 2 + 1] - mnew);
                rs += p0 + p1;
                __half2 ph = __floats2half2_rn(p0, p1);
                if (hh == 0) pa_lo[nt] = reinterpret_cast<uint32_t&>(ph);
                else         pa_hi[nt] = reinterpret_cast<uint32_t&>(ph);
                o[nt][hh * 2]     *= sc;
                o[nt][hh * 2 + 1] *= sc;
            }
            rs += __shfl_xor_sync(0xffffffffu, rs, 1);
            rs += __shfl_xor_sync(0xffffffffu, rs, 2);
            l_i[hh] = l_i[hh] * sc + rs;
        }

        // ---- O += P V  (A-frags direct from registers, B = V via ldmatrix.trans) ----
#pragma unroll
        for (int ks = 0; ks < 4; ks++) {
            uint32_t pa[4];
            pa[0] = pa_lo[2 * ks];     pa[1] = pa_hi[2 * ks];
            pa[2] = pa_lo[2 * ks + 1]; pa[3] = pa_hi[2 * ks + 1];
            uint32_t bf[8][2];
#pragma unroll
            for (int n4 = 0; n4 < 4; n4++) {
                uint32_t tmp[4];
                ldsm4t(tmp, Vst + ((ks * 16 + ldmr) * LD + n4 * 16 + ldmc) * 2);
                bf[n4 * 2][0]     = tmp[0]; bf[n4 * 2][1]     = tmp[1];
                bf[n4 * 2 + 1][0] = tmp[2]; bf[n4 * 2 + 1][1] = tmp[3];
            }
#pragma unroll
            for (int nt = 0; nt < 8; nt++)
                mma16(o[nt], pa, bf[nt]);
        }
    }

    // ---- normalize + write [S,B,E] fp16 for the output GEMM ----
#pragma unroll
    for (int hh = 0; hh < 2; hh++) {
        const float inv = 1.0f / l_i[hh];
        const int srow = qt * 128 + wid * 16 + g + hh * 8;
        __half* dst = g_attn + ((size_t)srow * BATCH + b) * EMB + head * HDIM + 2 * q;
#pragma unroll
        for (int nt = 0; nt < 8; nt++) {
            *(__half2*)(dst + nt * 8) =
                __floats2half2_rn(o[nt][hh * 2] * inv, o[nt][hh * 2 + 1] * inv);
        }
    }
}

extern "C" void kernel_launch(void* const* d_in, const int* in_sizes, int n_in,
                              void* d_out, int out_size)
{
    const float* query         = (const float*)d_in[0];
    const float* amask         = (const float*)d_in[1];
    const unsigned char* pmask = (const unsigned char*)d_in[2];
    const float* W_in          = (const float*)d_in[3];
    const float* b_in          = (const float*)d_in[4];
    const float* W_out         = (const float*)d_in[5];
    const float* b_out         = (const float*)d_in[6];
    float* out = (float*)d_out;
    (void)in_sizes; (void)n_in; (void)out_size;

    const int GEMM_SMEM = 8 * 128 * 40 * 2;                     // 81920 B (4 stages A+B)
    const int ATTN_SMEM = (128 * 72 + 8 * 64 * 72) * 2;         // 92160 B
    cudaFuncSetAttribute(gemm_fp16<0>, cudaFuncAttributeMaxDynamicSharedMemorySize, GEMM_SMEM);
    cudaFuncSetAttribute(gemm_fp16<1>, cudaFuncAttributeMaxDynamicSharedMemorySize, GEMM_SMEM);
    cudaFuncSetAttribute(attn_fp16,    cudaFuncAttributeMaxDynamicSharedMemorySize, ATTN_SMEM);

    __half* d_qr; __half* d_winr; __half* d_woutr; __half* d_maskh;
    cudaGetSymbolAddress((void**)&d_qr,    g_qr);
    cudaGetSymbolAddress((void**)&d_winr,  g_winr);
    cudaGetSymbolAddress((void**)&d_woutr, g_woutr);
    cudaGetSymbolAddress((void**)&d_maskh, g_maskh);

    // 0) conversion prepasses (pure HBM)
    cvt_fp16<<<SEQ*BATCH*EMB/1024, 256>>>(query, d_qr,    SEQ*BATCH*EMB);
    cvt_fp16<<<3*EMB*EMB/1024,     256>>>(W_in,  d_winr,  3*EMB*EMB);
    cvt_fp16<<<EMB*EMB/1024,       256>>>(W_out, d_woutr, EMB*EMB);
    prep_mask<<<BATCH*SEQ*SEQ/1024, 256>>>(amask, pmask, d_maskh);

    // 1) QKV projection, fused routing + q scaling (exp2 domain)
    gemm_fp16<0><<<dim3(24, 64), 256, GEMM_SMEM>>>(d_winr, b_in, nullptr);
    // 2) flash attention
    attn_fp16<<<dim3(16, 64), 256, ATTN_SMEM>>>();
    // 3) output projection
    gemm_fp16<1><<<dim3(8, 64), 256, GEMM_SMEM>>>(d_woutr, b_out, out);
}